// round 13
// baseline (speedup 1.0000x reference)
#include <cuda_runtime.h>
#include <cstdint>

#define NN    20000
#define NPAD  20096   // 157 * 128
#define NE    320000

// ---------------- scratch (static device memory, no allocs) ----------------
__device__ float  g_H[(size_t)NPAD * 16];
__device__ float  g_A[(size_t)NPAD * 1024];   // GEMM1 outputs (fp32, gathered by k_agg)
__device__ float  g_B[(size_t)NPAD * 1024];   // GEMM2/head outputs (fp32)
__device__ int8_t g_Aq1[(size_t)NPAD * 1024]; // activation quant (main)
__device__ int8_t g_Aq2[(size_t)NPAD * 1024]; // activation quant (residual)
__device__ float  g_sA[NPAD];                 // activation row scales
__device__ int8_t g_Wq1[5095424];             // weight quant (main), [N,K] transposed
__device__ int8_t g_Wq2[5095424];             // weight quant (residual)
__device__ float  g_sW[6272];                 // weight row scales
// CSR by destination
__device__ int    g_icnt[NPAD];
__device__ int    g_off[NPAD + 1];
__device__ int    g_cur[NPAD];
__device__ int    g_srcs[NE];
__device__ float2 g_crel[NE];
__device__ float  g_inv[NPAD];
__device__ float  g_msk[NPAD];

#define OFF_L1W2 0L
#define OFF_L2W1 16384L
#define OFF_L2W2 49152L
#define OFF_L3W1 114688L
#define OFF_L3W2 376832L
#define OFF_L4W1 1425408L
#define OFF_L4W2 2473984L
#define OFF_HDW1 3522560L
#define OFF_HDW2 4571136L
#define SOF_L1W2 0
#define SOF_L2W1 128
#define SOF_L2W2 384
#define SOF_L3W1 640
#define SOF_L3W2 1664
#define SOF_L4W1 2688
#define SOF_L4W2 3712
#define SOF_HDW1 4736
#define SOF_HDW2 5760

__device__ __forceinline__ void quant2(float x, int8_t& q1, int8_t& q2) {
    float q1f = rintf(x);
    float r = x - q1f;
    float q2f = fminf(fmaxf(rintf(r * 254.f), -127.f), 127.f);
    q1 = (int8_t)(int)q1f;
    q2 = (int8_t)(int)q2f;
}

// ---------------- prep kernels ----------------
__global__ void k_copy_h(const float* __restrict__ src) {
    int i = blockIdx.x * blockDim.x + threadIdx.x;
    if (i < NPAD * 16 / 4) {
        float4 v = (i < NN * 16 / 4) ? ((const float4*)src)[i] : make_float4(0.f, 0.f, 0.f, 0.f);
        ((float4*)g_H)[i] = v;
    }
    if (i < NPAD) g_icnt[i] = 0;
}

__global__ void k_count(const int* __restrict__ ei) {
    int e = blockIdx.x * blockDim.x + threadIdx.x;
    if (e < NE) atomicAdd(&g_icnt[ei[NE + e]], 1);
}

__global__ __launch_bounds__(1024) void k_scan() {
    __shared__ int sh[1024];
    __shared__ int carry;
    int tid = threadIdx.x;
    if (tid == 0) carry = 0;
    __syncthreads();
    for (int base = 0; base < NPAD; base += 1024) {
        int i = base + tid;
        int v = (i < NPAD) ? g_icnt[i] : 0;
        sh[tid] = v;
        __syncthreads();
#pragma unroll
        for (int off = 1; off < 1024; off <<= 1) {
            int t = (tid >= off) ? sh[tid - off] : 0;
            __syncthreads();
            if (tid >= off) sh[tid] += t;
            __syncthreads();
        }
        int incl = sh[tid];
        int c = carry;
        if (i < NPAD) {
            g_off[i] = c + incl - v;
            g_cur[i] = c + incl - v;
            float cf = (float)v;
            g_inv[i] = 1.0f / fmaxf(cf, 1.0f);
            g_msk[i] = (v > 0) ? 1.0f : 0.0f;
        }
        __syncthreads();
        if (tid == 1023) carry = c + incl;
        __syncthreads();
    }
    if (tid == 0) g_off[NPAD] = carry;
}

__global__ void k_scatter(const int* __restrict__ ei, const float* __restrict__ pos) {
    int e = blockIdx.x * blockDim.x + threadIdx.x;
    if (e < NE) {
        int s = ei[e];
        int d = ei[NE + e];
        int p = atomicAdd(&g_cur[d], 1);
        g_srcs[p] = s;
        float2 ps = ((const float2*)pos)[s];
        float2 pd = ((const float2*)pos)[d];
        g_crel[p] = make_float2(ps.x - pd.x, ps.y - pd.y);
    }
}

// ---------------- weight quantization ----------------
__global__ void k_wmax(const float* __restrict__ W, int K, int N, int soff) {
    int n = blockIdx.x * blockDim.x + threadIdx.x;
    if (n >= N) return;
    float m = 0.f;
    for (int k = 0; k < K; k++) m = fmaxf(m, fabsf(W[(long)k * N + n]));
    g_sW[soff + n] = (m > 0.f) ? m / 127.f : 1.f;
}

__global__ void k_wquant(const float* __restrict__ W, int K, int N, long woff, int soff) {
    __shared__ float tile[32][33];
    int bx = blockIdx.x, by = blockIdx.y;
    int tx = threadIdx.x, ty = threadIdx.y;  // block (32,8)
#pragma unroll
    for (int j = 0; j < 4; j++) {
        int k = by * 32 + ty + j * 8;
        int n = bx * 32 + tx;
        tile[ty + j * 8][tx] = W[(long)k * N + n];
    }
    __syncthreads();
#pragma unroll
    for (int j = 0; j < 4; j++) {
        int n = bx * 32 + ty + j * 8;
        int k = by * 32 + tx;
        float s = g_sW[soff + n];
        float x = tile[tx][ty + j * 8] / s;
        int8_t q1, q2;
        quant2(x, q1, q2);
        g_Wq1[woff + (long)n * K + k] = q1;
        g_Wq2[woff + (long)n * K + k] = q2;
    }
}

// ---------------- mma helpers ----------------
__device__ __forceinline__ void ldsm4(uint32_t& r0, uint32_t& r1, uint32_t& r2, uint32_t& r3,
                                      const void* p) {
    uint32_t addr = (uint32_t)__cvta_generic_to_shared(p);
    asm volatile("ldmatrix.sync.aligned.m8n8.x4.shared.b16 {%0,%1,%2,%3}, [%4];\n"
                 : "=r"(r0), "=r"(r1), "=r"(r2), "=r"(r3) : "r"(addr));
}

__device__ __forceinline__ void imma(int* c, const uint32_t* a, uint32_t b0, uint32_t b1) {
    asm volatile(
        "mma.sync.aligned.m16n8k32.row.col.s32.s8.s8.s32 "
        "{%0,%1,%2,%3}, {%4,%5,%6,%7}, {%8,%9}, {%0,%1,%2,%3};\n"
        : "+r"(c[0]), "+r"(c[1]), "+r"(c[2]), "+r"(c[3])
        : "r"(a[0]), "r"(a[1]), "r"(a[2]), "r"(a[3]), "r"(b0), "r"(b1));
}

__device__ __forceinline__ void cpasync16(uint32_t saddr, const void* gptr) {
    asm volatile("cp.async.cg.shared.global [%0], [%1], 16;\n" :: "r"(saddr), "l"(gptr));
}

// ---------------- int8 tensor-core GEMM v3: 64x128 tile, 256 thr, 2 CTAs/SM, 3-stage ----------------
// C[M=NPAD, N] = dequant( Aq[M,K] @ Wq[N,K]^T ), per-row scales g_sA, per-col g_sW.
template <bool RELU, bool SCALED>
__global__ __launch_bounds__(256, 2) void igemm_kernel(
    int K, int N, int f32Sel, long woff, int soff, const float* __restrict__ bias)
{
    constexpr int BK = 64;               // int8 K per chunk (64B rows)
    constexpr int PITCH = 80;
    constexpr int APLANE = 64 * PITCH;   // 5120 B
    constexpr int BPLANE = 128 * PITCH;  // 10240 B
    constexpr int STAGE = 2 * APLANE + 2 * BPLANE;  // 30720
    constexpr int NSTAGE = 3;
    extern __shared__ __align__(16) char smem[];
    const uint32_t sbase = (uint32_t)__cvta_generic_to_shared(smem);

    const int8_t* Wq1 = g_Wq1 + woff;
    const int8_t* Wq2 = g_Wq2 + woff;

    const int bm = blockIdx.y * 64;
    const int bn = blockIdx.x * 128;
    const int tid  = threadIdx.x;
    const int warp = tid >> 5;
    const int lane = tid & 31;
    const int warp_m = warp >> 2;   // 0..1
    const int warp_n = warp & 3;    // 0..3

    int accM[2][4][4], accC[2][4][4];
#pragma unroll
    for (int i = 0; i < 2; i++)
#pragma unroll
        for (int j = 0; j < 4; j++)
#pragma unroll
            for (int r = 0; r < 4; r++) { accM[i][j][r] = 0; accC[i][j][r] = 0; }

    const int a_row = lane & 15;
    const int a_koffB = ((lane >> 4) << 4);
    const int b_row = (lane & 7) + ((lane & 16) >> 1);
    const int b_koffB = (lane & 8) * 2;

    const int nChunk = K / BK;

    auto issue = [&](int stage, int k0) {
        uint32_t sb = sbase + stage * STAGE;
        {
            int row = tid >> 2;
            int seg = tid & 3;
            uint32_t so = sb + row * PITCH + seg * 16;
            long aoff = (long)(bm + row) * K + k0 + seg * 16;
            cpasync16(so,          g_Aq1 + aoff);
            cpasync16(so + APLANE, g_Aq2 + aoff);
        }
#pragma unroll
        for (int i = 0; i < 2; i++) {
            int idx = tid + i * 256;
            int row = idx >> 2;
            int seg = idx & 3;
            uint32_t so = sb + 2 * APLANE + row * PITCH + seg * 16;
            long boff = (long)(bn + row) * K + k0 + seg * 16;
            cpasync16(so,          Wq1 + boff);
            cpasync16(so + BPLANE, Wq2 + boff);
        }
        asm volatile("cp.async.commit_group;\n" ::: "memory");
    };

    // prime up to 3 stages
    issue(0, 0);
    if (nChunk > 1) issue(1, BK);
    if (nChunk > 2) issue(2, 2 * BK);

    for (int c = 0; c < nChunk; c++) {
        int s = c % NSTAGE;
        int ahead = nChunk - c - 1;         // chunks still in flight after c completes
        if (ahead >= 2)
            asm volatile("cp.async.wait_group 2;\n" ::: "memory");
        else if (ahead == 1)
            asm volatile("cp.async.wait_group 1;\n" ::: "memory");
        else
            asm volatile("cp.async.wait_group 0;\n" ::: "memory");
        __syncthreads();

        char* sA1 = smem + s * STAGE;
        char* sA2 = sA1 + APLANE;
        char* sB1 = sA1 + 2 * APLANE;
        char* sB2 = sB1 + BPLANE;

#pragma unroll
        for (int ksB = 0; ksB < 64; ksB += 32) {
            uint32_t aq1[2][4], aq2[2][4];
#pragma unroll
            for (int mt = 0; mt < 2; mt++) {
                int m0 = warp_m * 32 + mt * 16;
                ldsm4(aq1[mt][0], aq1[mt][1], aq1[mt][2], aq1[mt][3],
                      sA1 + (m0 + a_row) * PITCH + ksB + a_koffB);
                ldsm4(aq2[mt][0], aq2[mt][1], aq2[mt][2], aq2[mt][3],
                      sA2 + (m0 + a_row) * PITCH + ksB + a_koffB);
            }
#pragma unroll
            for (int pair = 0; pair < 2; pair++) {
                int n0 = warp_n * 32 + pair * 16;
                uint32_t b1_0, b1_1, b1_2, b1_3, b2_0, b2_1, b2_2, b2_3;
                ldsm4(b1_0, b1_1, b1_2, b1_3, sB1 + (n0 + b_row) * PITCH + ksB + b_koffB);
                ldsm4(b2_0, b2_1, b2_2, b2_3, sB2 + (n0 + b_row) * PITCH + ksB + b_koffB);
#pragma unroll
                for (int mt = 0; mt < 2; mt++) {
                    int* m0p = accM[mt][pair * 2 + 0];
                    int* c0p = accC[mt][pair * 2 + 0];
                    int* m1p = accM[mt][pair * 2 + 1];
                    int* c1p = accC[mt][pair * 2 + 1];
                    imma(m0p, aq1[mt], b1_0, b1_1);
                    imma(c0p, aq1[mt], b2_0, b2_1);
                    imma(c0p, aq2[mt], b1_0, b1_1);
                    imma(m1p, aq1[mt], b1_2, b1_3);
                    imma(c1p, aq1[mt], b2_2, b2_3);
                    imma(c1p, aq2[mt], b1_2, b1_3);
                }
            }
        }
        __syncthreads();

        if (c + NSTAGE < nChunk) issue(s, (c + NSTAGE) * BK);
    }

    // epilogue: dequant + bias(+mask) + optional relu, fp32 out
    float* Cf = (f32Sel == 1) ? g_A : g_B;
    const int rbase = bm + warp_m * 32 + (lane >> 2);
    const int cbase = bn + warp_n * 32 + 2 * (lane & 3);
    constexpr float INV254 = 1.f / 254.f;
#pragma unroll
    for (int mt = 0; mt < 2; mt++) {
#pragma unroll
        for (int half = 0; half < 2; half++) {
            int r = rbase + mt * 16 + half * 8;
            float sa = g_sA[r];
            float bmsk = SCALED ? g_msk[r] : 1.0f;
#pragma unroll
            for (int p = 0; p < 4; p++) {
                int c = cbase + p * 8;
                float2 sw = *(const float2*)(g_sW + soff + c);
                float2 bv = *(const float2*)(bias + c);
                float d0 = (float)accM[mt][p][half * 2 + 0]
                         + (float)accC[mt][p][half * 2 + 0] * INV254;
                float d1 = (float)accM[mt][p][half * 2 + 1]
                         + (float)accC[mt][p][half * 2 + 1] * INV254;
                float v0 = sa * sw.x * d0 + bv.x * bmsk;
                float v1 = sa * sw.y * d1 + bv.y * bmsk;
                if (RELU) { v0 = fmaxf(v0, 0.f); v1 = fmaxf(v1, 0.f); }
                *(float2*)(Cf + (long)r * N + c) = make_float2(v0, v1);
            }
        }
    }
}

// ---------------- SIMT SGEMM for K=16 first layer (g_H -> g_A) ----------------
__global__ __launch_bounds__(256) void sgemm16_kernel(
    int N, const float* __restrict__ B, const float* __restrict__ bias)
{
    constexpr int BM = 128, BK = 16, TM = 8, TN = 8;
    __shared__ __align__(16) float As[BK][BM];
    __shared__ __align__(16) float Bs[BK][128];
    const int bm = blockIdx.y * BM;
    const int bn = blockIdx.x * 128;
    const int tid = threadIdx.x;
    const int arow = tid >> 2, acol = (tid & 3) << 2;
    const int brow = tid >> 5, bcol = (tid & 31) << 2;
    const int ty = (tid >> 4) * TM, tx = (tid & 15) * TN;
    float acc[TM][TN];
#pragma unroll
    for (int i = 0; i < TM; i++)
#pragma unroll
        for (int j = 0; j < TN; j++) acc[i][j] = 0.f;
    const int K = 16;
#pragma unroll
    for (int i = 0; i < 2; i++) {
        int r = arow + i * 64;
        float4 v = *(const float4*)(g_H + (long)(bm + r) * K + acol);
        As[acol + 0][r] = v.x; As[acol + 1][r] = v.y;
        As[acol + 2][r] = v.z; As[acol + 3][r] = v.w;
    }
#pragma unroll
    for (int i = 0; i < 2; i++) {
        int r = brow + i * 8;
        *(float4*)(&Bs[r][bcol]) = *(const float4*)(B + (long)r * N + bn + bcol);
    }
    __syncthreads();
#pragma unroll
    for (int kk = 0; kk < BK; kk++) {
        float ra[TM], rb[TN];
        *(float4*)(ra)     = *(const float4*)(&As[kk][ty]);
        *(float4*)(ra + 4) = *(const float4*)(&As[kk][ty + 4]);
        *(float4*)(rb)     = *(const float4*)(&Bs[kk][tx]);
        *(float4*)(rb + 4) = *(const float4*)(&Bs[kk][tx + 4]);
#pragma unroll
        for (int i = 0; i < TM; i++)
#pragma unroll
            for (int j = 0; j < TN; j++) acc[i][j] += ra[i] * rb[j];
    }
#pragma unroll
    for (int i = 0; i < TM; i++) {
        long m = bm + ty + i;
        float* crow = g_A + m * N + bn + tx;
#pragma unroll
        for (int j = 0; j < TN; j += 4) {
            float4 bv = *(const float4*)(bias + bn + tx + j);
            float4 o;
            o.x = acc[i][j + 0] + bv.x; o.y = acc[i][j + 1] + bv.y;
            o.z = acc[i][j + 2] + bv.z; o.w = acc[i][j + 3] + bv.w;
            *(float4*)(crow + j) = o;
        }
    }
}

// ---------------- CSR aggregation with fused double-quantization ----------------
template <int H, int RPB>
__global__ __launch_bounds__(256) void k_agg(const float* __restrict__ w1p) {
    constexpr int TPR = H / 4;
    static_assert(TPR * RPB == 256, "block mapping");
    __shared__ __align__(16) float sw0[H];
    __shared__ __align__(16) float sw1[H];
    __shared__ float smax[256];
    for (int i = threadIdx.x; i < H; i += 256) {
        sw0[i] = w1p[i];
        sw1[i] = w1p[H + i];
    }
    __syncthreads();

    const int lr   = threadIdx.x / TPR;
    const int lane = threadIdx.x % TPR;
    const int row  = blockIdx.x * RPB + lr;
    const int v    = lane * 4;

    const float4 w0 = *(const float4*)(sw0 + v);
    const float4 w1 = *(const float4*)(sw1 + v);

    const int beg = g_off[row];
    const int end = g_off[row + 1];

    float4 acc = make_float4(0.f, 0.f, 0.f, 0.f);
    for (int j = beg; j < end; j++) {
        int src = __ldg(g_srcs + j);
        float2 rp = __ldg(g_crel + j);
        float4 a = *(const float4*)(g_A + (long)src * H + v);
        acc.x += fmaxf(fmaf(rp.x, w0.x, fmaf(rp.y, w1.x, a.x)), 0.f);
        acc.y += fmaxf(fmaf(rp.x, w0.y, fmaf(rp.y, w1.y, a.y)), 0.f);
        acc.z += fmaxf(fmaf(rp.x, w0.z, fmaf(rp.y, w1.z, a.z)), 0.f);
        acc.w += fmaxf(fmaf(rp.x, w0.w, fmaf(rp.y, w1.w, a.w)), 0.f);
    }
    float s = g_inv[row];
    acc.x *= s; acc.y *= s; acc.z *= s; acc.w *= s;

    smax[threadIdx.x] = fmaxf(fmaxf(acc.x, acc.y), fmaxf(acc.z, acc.w));
    __syncthreads();
    const int gb = lr * TPR;
#pragma unroll
    for (int st = TPR >> 1; st > 0; st >>= 1) {
        if (lane < st) smax[gb + lane] = fmaxf(smax[gb + lane], smax[gb + lane + st]);
        __syncthreads();
    }
    float rm = smax[gb];
    float sc = (rm > 0.f) ? rm / 127.f : 1.f;
    if (lane == 0) g_sA[row] = sc;
    float isc = 1.f / sc;

    int8_t q1[4], q2[4];
    quant2(acc.x * isc, q1[0], q2[0]);
    quant2(acc.y * isc, q1[1], q2[1]);
    quant2(acc.z * isc, q1[2], q2[2]);
    quant2(acc.w * isc, q1[3], q2[3]);
    long o = (long)row * H + v;
    *(char4*)(g_Aq1 + o) = make_char4(q1[0], q1[1], q1[2], q1[3]);
    *(char4*)(g_Aq2 + o) = make_char4(q2[0], q2[1], q2[2], q2[3]);
}

// ---------------- quantize fp32 g_B rows -> g_Aq1/g_Aq2 + g_sA ----------------
__global__ void k_aquant(int N) {
    __shared__ float smax[256];
    int row = blockIdx.x;
    int t = threadIdx.x;
    float4 xv = ((const float4*)(g_B + (long)row * N))[t];
    float m = fmaxf(fmaxf(fabsf(xv.x), fabsf(xv.y)), fmaxf(fabsf(xv.z), fabsf(xv.w)));
    smax[t] = m;
    __syncthreads();
    for (int st = blockDim.x >> 1; st > 0; st >>= 1) {
        if (t < st) smax[t] = fmaxf(smax[t], smax[t + st]);
        __syncthreads();
    }
    float rm = smax[0];
    float sc = (rm > 0.f) ? rm / 127.f : 1.f;
    if (t == 0) g_sA[row] = sc;
    float isc = 1.f / sc;
    int8_t q1[4], q2[4];
    quant2(xv.x * isc, q1[0], q2[0]);
    quant2(xv.y * isc, q1[1], q2[1]);
    quant2(xv.z * isc, q1[2], q2[2]);
    quant2(xv.w * isc, q1[3], q2[3]);
    long o = (long)row * N + t * 4;
    *(char4*)(g_Aq1 + o) = make_char4(q1[0], q1[1], q1[2], q1[3]);
    *(char4*)(g_Aq2 + o) = make_char4(q2[0], q2[1], q2[2], q2[3]);
}

// ---------------- head final ----------------
__global__ void k_head_final(const float* __restrict__ W,
                             const float* __restrict__ b, float* __restrict__ out) {
    int warp = (blockIdx.x * blockDim.x + threadIdx.x) >> 5;
    int lane = threadIdx.x & 31;
    if (warp >= NN) return;
    const float* x = g_B + (long)warp * 512;
    float a0 = 0.f, a1 = 0.f, a2 = 0.f, a3 = 0.f;
    for (int k = lane; k < 512; k += 32) {
        float xv = x[k];
        float4 w = *(const float4*)(W + k * 4);
        a0 = fmaf(xv, w.x, a0);
        a1 = fmaf(xv, w.y, a1);
        a2 = fmaf(xv, w.z, a2);
        a3 = fmaf(xv, w.w, a3);
    }
#pragma unroll
    for (int off = 16; off > 0; off >>= 1) {
        a0 += __shfl_down_sync(0xffffffffu, a0, off);
        a1 += __shfl_down_sync(0xffffffffu, a1, off);
        a2 += __shfl_down_sync(0xffffffffu, a2, off);
        a3 += __shfl_down_sync(0xffffffffu, a3, off);
    }
    if (lane == 0) {
        out[warp * 4 + 0] = a0 + b[0];
        out[warp * 4 + 1] = a1 + b[1];
        out[warp * 4 + 2] = a2 + b[2];
        out[warp * 4 + 3] = a3 + b[3];
    }
}

// ---------------- host orchestration ----------------
#define IG_SMEM (3 * 30720)   // 92160

template <bool RELU, bool SCALED>
static void launch_ig(dim3 grid, int K, int N, int f32Sel, long woff, int soff,
                      const float* bias) {
    cudaFuncSetAttribute(igemm_kernel<RELU, SCALED>,
                         cudaFuncAttributeMaxDynamicSharedMemorySize, IG_SMEM);
    igemm_kernel<RELU, SCALED><<<grid, 256, IG_SMEM>>>(K, N, f32Sel, woff, soff, bias);
}

static void wprep(const float* W, int K, int N, long woff, int soff) {
    k_wmax<<<(N + 255) / 256, 256>>>(W, K, N, soff);
    k_wquant<<<dim3(N / 32, K / 32), dim3(32, 8)>>>(W, K, N, woff, soff);
}

extern "C" void kernel_launch(void* const* d_in, const int* in_sizes, int n_in,
                              void* d_out, int out_size) {
    const float* h_in = (const float*)d_in[0];
    const float* pos  = (const float*)d_in[1];
    const int*   ei   = (const int*)d_in[2];
    const float* l1_w1 = (const float*)d_in[3];
    const float* l1_b1 = (const float*)d_in[4];
    const float* l1_w2 = (const float*)d_in[5];
    const float* l1_b2 = (const float*)d_in[6];
    const float* l2_w1 = (const float*)d_in[7];
    const float* l2_b1 = (const float*)d_in[8];
    const float* l2_w2 = (const float*)d_in[9];
    const float* l2_b2 = (const float*)d_in[10];
    const float* l3_w1 = (const float*)d_in[11];
    const float* l3_b1 = (const float*)d_in[12];
    const float* l3_w2 = (const float*)d_in[13];
    const float* l3_b2 = (const float*)d_in[14];
    const float* l4_w1 = (const float*)d_in[15];
    const float* l4_b1 = (const float*)d_in[16];
    const float* l4_w2 = (const float*)d_in[17];
    const float* l4_b2 = (const float*)d_in[18];
    const float* hd_w1 = (const float*)d_in[19];
    const float* hd_b1 = (const float*)d_in[20];
    const float* hd_w2 = (const float*)d_in[21];
    const float* hd_b2 = (const float*)d_in[22];
    const float* hd_w3 = (const float*)d_in[23];
    const float* hd_b3 = (const float*)d_in[24];

    // prep: padded copy + CSR build
    k_copy_h<<<(NPAD * 16 / 4 + 255) / 256, 256>>>(h_in);
    k_count<<<(NE + 255) / 256, 256>>>(ei);
    k_scan<<<1, 1024>>>();
    k_scatter<<<(NE + 255) / 256, 256>>>(ei, pos);

    dim3 g1s(1, NPAD / 128);
    dim3 g128(1, NPAD / 64), g256(2, NPAD / 64), g1024(8, NPAD / 64), g512(4, NPAD / 64);

    // layer 1 front half (fp32)
    sgemm16_kernel<<<g1s, 256>>>(128, l1_w1, l1_b1);
    k_agg<128, 8><<<NPAD / 8, 256>>>(l1_w1 + 16 * 128);

    // weight quantization (transposed double-quant int8)
    wprep(l1_w2, 128, 128, OFF_L1W2, SOF_L1W2);
    wprep(l2_w1, 128, 256, OFF_L2W1, SOF_L2W1);
    wprep(l2_w2, 256, 256, OFF_L2W2, SOF_L2W2);
    wprep(l3_w1, 256, 1024, OFF_L3W1, SOF_L3W1);
    wprep(l3_w2, 1024, 1024, OFF_L3W2, SOF_L3W2);
    wprep(l4_w1, 1024, 1024, OFF_L4W1, SOF_L4W1);
    wprep(l4_w2, 1024, 1024, OFF_L4W2, SOF_L4W2);
    wprep(hd_w1, 1024, 1024, OFF_HDW1, SOF_HDW1);
    wprep(hd_w2, 1024, 512, OFF_HDW2, SOF_HDW2);

    // --- layer 1 back half ---
    launch_ig<true, true>(g128, 128, 128, 0, OFF_L1W2, SOF_L1W2, l1_b2);
    k_aquant<<<NPAD, 128 / 4>>>(128);

    // --- layer 2 ---
    launch_ig<false, false>(g256, 128, 256, 1, OFF_L2W1, SOF_L2W1, l2_b1);
    k_agg<256, 4><<<NPAD / 4, 256>>>(l2_w1 + 128 * 256);
    launch_ig<true, true>(g256, 256, 256, 0, OFF_L2W2, SOF_L2W2, l2_b2);
    k_aquant<<<NPAD, 256 / 4>>>(256);

    // --- layer 3 ---
    launch_ig<false, false>(g1024, 256, 1024, 1, OFF_L3W1, SOF_L3W1, l3_b1);
    k_agg<1024, 1><<<NPAD, 256>>>(l3_w1 + 256 * 1024);
    launch_ig<true, true>(g1024, 1024, 1024, 0, OFF_L3W2, SOF_L3W2, l3_b2);
    k_aquant<<<NPAD, 1024 / 4>>>(1024);

    // --- layer 4 ---
    launch_ig<false, false>(g1024, 1024, 1024, 1, OFF_L4W1, SOF_L4W1, l4_b1);
    k_agg<1024, 1><<<NPAD, 256>>>(l4_w1 + 1024 * 1024);
    launch_ig<true, true>(g1024, 1024, 1024, 0, OFF_L4W2, SOF_L4W2, l4_b2);
    k_aquant<<<NPAD, 1024 / 4>>>(1024);

    // --- head ---
    launch_ig<true, false>(g1024, 1024, 1024, 0, OFF_HDW1, SOF_HDW1, hd_b1);
    k_aquant<<<NPAD, 1024 / 4>>>(1024);
    launch_ig<true, false>(g512, 1024, 512, 0, OFF_HDW2, SOF_HDW2, hd_b2);
    k_head_final<<<(NN * 32 + 255) / 256, 256>>>(hd_w3, hd_b3, (float*)d_out);
}

// round 14
// speedup vs baseline: 1.1196x; 1.1196x over previous
#include <cuda_runtime.h>
#include <cstdint>

#define NN    20000
#define NPAD  20096   // 157 * 128
#define NE    320000

// ---------------- scratch (static device memory, no allocs) ----------------
__device__ float  g_H[(size_t)NPAD * 16];
__device__ float  g_A[(size_t)NPAD * 1024];   // GEMM1 outputs (fp32, gathered by k_agg)
__device__ float  g_B[(size_t)NPAD * 1024];   // GEMM2/head outputs (fp32)
__device__ int8_t g_Aq1[(size_t)NPAD * 1024]; // activation quant (main)
__device__ int8_t g_Aq2[(size_t)NPAD * 1024]; // activation quant (residual)
__device__ float  g_sA[NPAD];                 // activation row scales
__device__ int8_t g_Wq1[5095424];             // weight quant (main), [N,K] transposed
__device__ int8_t g_Wq2[5095424];             // weight quant (residual)
__device__ float  g_sW[6272];                 // weight row scales
__device__ float  g_sWmax[6272];              // weight row |max| (atomicMax accum)
// CSR by destination
__device__ int    g_icnt[NPAD];
__device__ int    g_off[NPAD + 1];
__device__ int    g_cur[NPAD];
__device__ int    g_srcs[NE];
__device__ float2 g_crel[NE];
__device__ float  g_inv[NPAD];
__device__ float  g_msk[NPAD];

#define OFF_L1W2 0L
#define OFF_L2W1 16384L
#define OFF_L2W2 49152L
#define OFF_L3W1 114688L
#define OFF_L3W2 376832L
#define OFF_L4W1 1425408L
#define OFF_L4W2 2473984L
#define OFF_HDW1 3522560L
#define OFF_HDW2 4571136L
#define SOF_L1W2 0
#define SOF_L2W1 128
#define SOF_L2W2 384
#define SOF_L3W1 640
#define SOF_L3W2 1664
#define SOF_L4W1 2688
#define SOF_L4W2 3712
#define SOF_HDW1 4736
#define SOF_HDW2 5760

__device__ __forceinline__ void quant2(float x, int8_t& q1, int8_t& q2) {
    float q1f = rintf(x);
    float r = x - q1f;
    float q2f = fminf(fmaxf(rintf(r * 254.f), -127.f), 127.f);
    q1 = (int8_t)(int)q1f;
    q2 = (int8_t)(int)q2f;
}

// ---------------- prep kernels ----------------
__global__ void k_copy_h(const float* __restrict__ src) {
    int i = blockIdx.x * blockDim.x + threadIdx.x;
    if (i < NPAD * 16 / 4) {
        float4 v = (i < NN * 16 / 4) ? ((const float4*)src)[i] : make_float4(0.f, 0.f, 0.f, 0.f);
        ((float4*)g_H)[i] = v;
    }
    if (i < NPAD) g_icnt[i] = 0;
    if (i < 6272) g_sWmax[i] = 0.f;
}

__global__ void k_count(const int* __restrict__ ei) {
    int e = blockIdx.x * blockDim.x + threadIdx.x;
    if (e < NE) atomicAdd(&g_icnt[ei[NE + e]], 1);
}

__global__ __launch_bounds__(1024) void k_scan() {
    __shared__ int sh[1024];
    __shared__ int carry;
    int tid = threadIdx.x;
    if (tid == 0) carry = 0;
    __syncthreads();
    for (int base = 0; base < NPAD; base += 1024) {
        int i = base + tid;
        int v = (i < NPAD) ? g_icnt[i] : 0;
        sh[tid] = v;
        __syncthreads();
#pragma unroll
        for (int off = 1; off < 1024; off <<= 1) {
            int t = (tid >= off) ? sh[tid - off] : 0;
            __syncthreads();
            if (tid >= off) sh[tid] += t;
            __syncthreads();
        }
        int incl = sh[tid];
        int c = carry;
        if (i < NPAD) {
            g_off[i] = c + incl - v;
            g_cur[i] = c + incl - v;
            float cf = (float)v;
            g_inv[i] = 1.0f / fmaxf(cf, 1.0f);
            g_msk[i] = (v > 0) ? 1.0f : 0.0f;
        }
        __syncthreads();
        if (tid == 1023) carry = c + incl;
        __syncthreads();
    }
    if (tid == 0) g_off[NPAD] = carry;
}

__global__ void k_scatter(const int* __restrict__ ei, const float* __restrict__ pos) {
    int e = blockIdx.x * blockDim.x + threadIdx.x;
    if (e < NE) {
        int s = ei[e];
        int d = ei[NE + e];
        int p = atomicAdd(&g_cur[d], 1);
        g_srcs[p] = s;
        float2 ps = ((const float2*)pos)[s];
        float2 pd = ((const float2*)pos)[d];
        g_crel[p] = make_float2(ps.x - pd.x, ps.y - pd.y);
    }
}

// ---------------- weight quantization ----------------
// parallel per-column max: grid (ceil(N/256), 8), atomicMax on float bits (vals >= 0)
__global__ void k_wmax(const float* __restrict__ W, int K, int N, int soff) {
    int n = blockIdx.x * 256 + threadIdx.x;
    if (n >= N) return;
    int kchunk = K >> 3;
    int k0 = blockIdx.y * kchunk;
    float m = 0.f;
    for (int k = k0; k < k0 + kchunk; k++) m = fmaxf(m, fabsf(W[(long)k * N + n]));
    atomicMax((unsigned*)&g_sWmax[soff + n], __float_as_uint(m));
}

// transpose + double-quantize: W[K,N] -> q[N,K]; computes & stores scale from g_sWmax
__global__ void k_wquant(const float* __restrict__ W, int K, int N, long woff, int soff) {
    __shared__ float tile[32][33];
    int bx = blockIdx.x, by = blockIdx.y;
    int tx = threadIdx.x, ty = threadIdx.y;  // block (32,8)
#pragma unroll
    for (int j = 0; j < 4; j++) {
        int k = by * 32 + ty + j * 8;
        int n = bx * 32 + tx;
        tile[ty + j * 8][tx] = W[(long)k * N + n];
    }
    __syncthreads();
#pragma unroll
    for (int j = 0; j < 4; j++) {
        int n = bx * 32 + ty + j * 8;
        int k = by * 32 + tx;
        float mx = g_sWmax[soff + n];
        float s = (mx > 0.f) ? mx / 127.f : 1.f;
        if (tx == 0) g_sW[soff + n] = s;   // redundant same-value writes across K-blocks: benign
        float x = tile[tx][ty + j * 8] / s;
        int8_t q1, q2;
        quant2(x, q1, q2);
        g_Wq1[woff + (long)n * K + k] = q1;
        g_Wq2[woff + (long)n * K + k] = q2;
    }
}

// ---------------- mma helpers ----------------
__device__ __forceinline__ void ldsm4(uint32_t& r0, uint32_t& r1, uint32_t& r2, uint32_t& r3,
                                      const void* p) {
    uint32_t addr = (uint32_t)__cvta_generic_to_shared(p);
    asm volatile("ldmatrix.sync.aligned.m8n8.x4.shared.b16 {%0,%1,%2,%3}, [%4];\n"
                 : "=r"(r0), "=r"(r1), "=r"(r2), "=r"(r3) : "r"(addr));
}

__device__ __forceinline__ void imma(int* c, const uint32_t* a, uint32_t b0, uint32_t b1) {
    asm volatile(
        "mma.sync.aligned.m16n8k32.row.col.s32.s8.s8.s32 "
        "{%0,%1,%2,%3}, {%4,%5,%6,%7}, {%8,%9}, {%0,%1,%2,%3};\n"
        : "+r"(c[0]), "+r"(c[1]), "+r"(c[2]), "+r"(c[3])
        : "r"(a[0]), "r"(a[1]), "r"(a[2]), "r"(a[3]), "r"(b0), "r"(b1));
}

__device__ __forceinline__ void cpasync16(uint32_t saddr, const void* gptr) {
    asm volatile("cp.async.cg.shared.global [%0], [%1], 16;\n" :: "r"(saddr), "l"(gptr));
}

// ---------------- int8 tensor-core GEMM (R12-proven): 64x128 tile, 256 thr, 2 CTAs/SM, 2-stage ----------------
template <bool RELU, bool SCALED>
__global__ __launch_bounds__(256, 2) void igemm_kernel(
    int K, int N, int f32Sel, long woff, int soff, const float* __restrict__ bias)
{
    constexpr int BK = 64;
    constexpr int PITCH = 80;
    constexpr int APLANE = 64 * PITCH;
    constexpr int BPLANE = 128 * PITCH;
    constexpr int STAGE = 2 * APLANE + 2 * BPLANE;  // 30720
    extern __shared__ __align__(16) char smem[];
    const uint32_t sbase = (uint32_t)__cvta_generic_to_shared(smem);

    const int8_t* Wq1 = g_Wq1 + woff;
    const int8_t* Wq2 = g_Wq2 + woff;

    const int bm = blockIdx.y * 64;
    const int bn = blockIdx.x * 128;
    const int tid  = threadIdx.x;
    const int warp = tid >> 5;
    const int lane = tid & 31;
    const int warp_m = warp >> 2;
    const int warp_n = warp & 3;

    int accM[2][4][4], accC[2][4][4];
#pragma unroll
    for (int i = 0; i < 2; i++)
#pragma unroll
        for (int j = 0; j < 4; j++)
#pragma unroll
            for (int r = 0; r < 4; r++) { accM[i][j][r] = 0; accC[i][j][r] = 0; }

    const int a_row = lane & 15;
    const int a_koffB = ((lane >> 4) << 4);
    const int b_row = (lane & 7) + ((lane & 16) >> 1);
    const int b_koffB = (lane & 8) * 2;

    const int nChunk = K / BK;

    auto issue = [&](int stage, int k0) {
        uint32_t sb = sbase + stage * STAGE;
        {
            int row = tid >> 2;
            int seg = tid & 3;
            uint32_t so = sb + row * PITCH + seg * 16;
            long aoff = (long)(bm + row) * K + k0 + seg * 16;
            cpasync16(so,          g_Aq1 + aoff);
            cpasync16(so + APLANE, g_Aq2 + aoff);
        }
#pragma unroll
        for (int i = 0; i < 2; i++) {
            int idx = tid + i * 256;
            int row = idx >> 2;
            int seg = idx & 3;
            uint32_t so = sb + 2 * APLANE + row * PITCH + seg * 16;
            long boff = (long)(bn + row) * K + k0 + seg * 16;
            cpasync16(so,          Wq1 + boff);
            cpasync16(so + BPLANE, Wq2 + boff);
        }
        asm volatile("cp.async.commit_group;\n" ::: "memory");
    };

    issue(0, 0);
    if (nChunk > 1) issue(1, BK);

    for (int c = 0; c < nChunk; c++) {
        int s = c & 1;
        if (c + 1 < nChunk)
            asm volatile("cp.async.wait_group 1;\n" ::: "memory");
        else
            asm volatile("cp.async.wait_group 0;\n" ::: "memory");
        __syncthreads();

        char* sA1 = smem + s * STAGE;
        char* sA2 = sA1 + APLANE;
        char* sB1 = sA1 + 2 * APLANE;
        char* sB2 = sB1 + BPLANE;

#pragma unroll
        for (int ksB = 0; ksB < 64; ksB += 32) {
            uint32_t aq1[2][4], aq2[2][4];
#pragma unroll
            for (int mt = 0; mt < 2; mt++) {
                int m0 = warp_m * 32 + mt * 16;
                ldsm4(aq1[mt][0], aq1[mt][1], aq1[mt][2], aq1[mt][3],
                      sA1 + (m0 + a_row) * PITCH + ksB + a_koffB);
                ldsm4(aq2[mt][0], aq2[mt][1], aq2[mt][2], aq2[mt][3],
                      sA2 + (m0 + a_row) * PITCH + ksB + a_koffB);
            }
#pragma unroll
            for (int pair = 0; pair < 2; pair++) {
                int n0 = warp_n * 32 + pair * 16;
                uint32_t b1_0, b1_1, b1_2, b1_3, b2_0, b2_1, b2_2, b2_3;
                ldsm4(b1_0, b1_1, b1_2, b1_3, sB1 + (n0 + b_row) * PITCH + ksB + b_koffB);
                ldsm4(b2_0, b2_1, b2_2, b2_3, sB2 + (n0 + b_row) * PITCH + ksB + b_koffB);
#pragma unroll
                for (int mt = 0; mt < 2; mt++) {
                    int* m0p = accM[mt][pair * 2 + 0];
                    int* c0p = accC[mt][pair * 2 + 0];
                    int* m1p = accM[mt][pair * 2 + 1];
                    int* c1p = accC[mt][pair * 2 + 1];
                    imma(m0p, aq1[mt], b1_0, b1_1);
                    imma(c0p, aq1[mt], b2_0, b2_1);
                    imma(c0p, aq2[mt], b1_0, b1_1);
                    imma(m1p, aq1[mt], b1_2, b1_3);
                    imma(c1p, aq1[mt], b2_2, b2_3);
                    imma(c1p, aq2[mt], b1_2, b1_3);
                }
            }
        }
        __syncthreads();

        if (c + 2 < nChunk) issue(s, (c + 2) * BK);
    }

    float* Cf = (f32Sel == 1) ? g_A : g_B;
    const int rbase = bm + warp_m * 32 + (lane >> 2);
    const int cbase = bn + warp_n * 32 + 2 * (lane & 3);
    constexpr float INV254 = 1.f / 254.f;
#pragma unroll
    for (int mt = 0; mt < 2; mt++) {
#pragma unroll
        for (int half = 0; half < 2; half++) {
            int r = rbase + mt * 16 + half * 8;
            float sa = g_sA[r];
            float bmsk = SCALED ? g_msk[r] : 1.0f;
#pragma unroll
            for (int p = 0; p < 4; p++) {
                int c = cbase + p * 8;
                float2 sw = *(const float2*)(g_sW + soff + c);
                float2 bv = *(const float2*)(bias + c);
                float d0 = (float)accM[mt][p][half * 2 + 0]
                         + (float)accC[mt][p][half * 2 + 0] * INV254;
                float d1 = (float)accM[mt][p][half * 2 + 1]
                         + (float)accC[mt][p][half * 2 + 1] * INV254;
                float v0 = sa * sw.x * d0 + bv.x * bmsk;
                float v1 = sa * sw.y * d1 + bv.y * bmsk;
                if (RELU) { v0 = fmaxf(v0, 0.f); v1 = fmaxf(v1, 0.f); }
                *(float2*)(Cf + (long)r * N + c) = make_float2(v0, v1);
            }
        }
    }
}

// ---------------- SIMT SGEMM for K=16 first layer (g_H -> g_A) ----------------
__global__ __launch_bounds__(256) void sgemm16_kernel(
    int N, const float* __restrict__ B, const float* __restrict__ bias)
{
    constexpr int BM = 128, BK = 16, TM = 8, TN = 8;
    __shared__ __align__(16) float As[BK][BM];
    __shared__ __align__(16) float Bs[BK][128];
    const int bm = blockIdx.y * BM;
    const int bn = blockIdx.x * 128;
    const int tid = threadIdx.x;
    const int arow = tid >> 2, acol = (tid & 3) << 2;
    const int brow = tid >> 5, bcol = (tid & 31) << 2;
    const int ty = (tid >> 4) * TM, tx = (tid & 15) * TN;
    float acc[TM][TN];
#pragma unroll
    for (int i = 0; i < TM; i++)
#pragma unroll
        for (int j = 0; j < TN; j++) acc[i][j] = 0.f;
    const int K = 16;
#pragma unroll
    for (int i = 0; i < 2; i++) {
        int r = arow + i * 64;
        float4 v = *(const float4*)(g_H + (long)(bm + r) * K + acol);
        As[acol + 0][r] = v.x; As[acol + 1][r] = v.y;
        As[acol + 2][r] = v.z; As[acol + 3][r] = v.w;
    }
#pragma unroll
    for (int i = 0; i < 2; i++) {
        int r = brow + i * 8;
        *(float4*)(&Bs[r][bcol]) = *(const float4*)(B + (long)r * N + bn + bcol);
    }
    __syncthreads();
#pragma unroll
    for (int kk = 0; kk < BK; kk++) {
        float ra[TM], rb[TN];
        *(float4*)(ra)     = *(const float4*)(&As[kk][ty]);
        *(float4*)(ra + 4) = *(const float4*)(&As[kk][ty + 4]);
        *(float4*)(rb)     = *(const float4*)(&Bs[kk][tx]);
        *(float4*)(rb + 4) = *(const float4*)(&Bs[kk][tx + 4]);
#pragma unroll
        for (int i = 0; i < TM; i++)
#pragma unroll
            for (int j = 0; j < TN; j++) acc[i][j] += ra[i] * rb[j];
    }
#pragma unroll
    for (int i = 0; i < TM; i++) {
        long m = bm + ty + i;
        float* crow = g_A + m * N + bn + tx;
#pragma unroll
        for (int j = 0; j < TN; j += 4) {
            float4 bv = *(const float4*)(bias + bn + tx + j);
            float4 o;
            o.x = acc[i][j + 0] + bv.x; o.y = acc[i][j + 1] + bv.y;
            o.z = acc[i][j + 2] + bv.z; o.w = acc[i][j + 3] + bv.w;
            *(float4*)(crow + j) = o;
        }
    }
}

// ---------------- CSR aggregation with fused double-quantization (2-way unrolled gather) ----------------
template <int H, int RPB>
__global__ __launch_bounds__(256) void k_agg(const float* __restrict__ w1p) {
    constexpr int TPR = H / 4;
    static_assert(TPR * RPB == 256, "block mapping");
    __shared__ __align__(16) float sw0[H];
    __shared__ __align__(16) float sw1[H];
    __shared__ float smax[256];
    for (int i = threadIdx.x; i < H; i += 256) {
        sw0[i] = w1p[i];
        sw1[i] = w1p[H + i];
    }
    __syncthreads();

    const int lr   = threadIdx.x / TPR;
    const int lane = threadIdx.x % TPR;
    const int row  = blockIdx.x * RPB + lr;
    const int v    = lane * 4;

    const float4 w0 = *(const float4*)(sw0 + v);
    const float4 w1 = *(const float4*)(sw1 + v);

    const int beg = g_off[row];
    const int end = g_off[row + 1];

    float4 acc = make_float4(0.f, 0.f, 0.f, 0.f);
    int j = beg;
    for (; j + 2 <= end; j += 2) {
        int s0 = __ldg(g_srcs + j);
        int s1 = __ldg(g_srcs + j + 1);
        float2 r0 = __ldg(g_crel + j);
        float2 r1 = __ldg(g_crel + j + 1);
        float4 a0 = *(const float4*)(g_A + (long)s0 * H + v);
        float4 a1 = *(const float4*)(g_A + (long)s1 * H + v);
        acc.x += fmaxf(fmaf(r0.x, w0.x, fmaf(r0.y, w1.x, a0.x)), 0.f);
        acc.y += fmaxf(fmaf(r0.x, w0.y, fmaf(r0.y, w1.y, a0.y)), 0.f);
        acc.z += fmaxf(fmaf(r0.x, w0.z, fmaf(r0.y, w1.z, a0.z)), 0.f);
        acc.w += fmaxf(fmaf(r0.x, w0.w, fmaf(r0.y, w1.w, a0.w)), 0.f);
        acc.x += fmaxf(fmaf(r1.x, w0.x, fmaf(r1.y, w1.x, a1.x)), 0.f);
        acc.y += fmaxf(fmaf(r1.x, w0.y, fmaf(r1.y, w1.y, a1.y)), 0.f);
        acc.z += fmaxf(fmaf(r1.x, w0.z, fmaf(r1.y, w1.z, a1.z)), 0.f);
        acc.w += fmaxf(fmaf(r1.x, w0.w, fmaf(r1.y, w1.w, a1.w)), 0.f);
    }
    if (j < end) {
        int s0 = __ldg(g_srcs + j);
        float2 r0 = __ldg(g_crel + j);
        float4 a0 = *(const float4*)(g_A + (long)s0 * H + v);
        acc.x += fmaxf(fmaf(r0.x, w0.x, fmaf(r0.y, w1.x, a0.x)), 0.f);
        acc.y += fmaxf(fmaf(r0.x, w0.y, fmaf(r0.y, w1.y, a0.y)), 0.f);
        acc.z += fmaxf(fmaf(r0.x, w0.z, fmaf(r0.y, w1.z, a0.z)), 0.f);
        acc.w += fmaxf(fmaf(r0.x, w0.w, fmaf(r0.y, w1.w, a0.w)), 0.f);
    }
    float s = g_inv[row];
    acc.x *= s; acc.y *= s; acc.z *= s; acc.w *= s;

    smax[threadIdx.x] = fmaxf(fmaxf(acc.x, acc.y), fmaxf(acc.z, acc.w));
    __syncthreads();
    const int gb = lr * TPR;
#pragma unroll
    for (int st = TPR >> 1; st > 0; st >>= 1) {
        if (lane < st) smax[gb + lane] = fmaxf(smax[gb + lane], smax[gb + lane + st]);
        __syncthreads();
    }
    float rm = smax[gb];
    float sc = (rm > 0.f) ? rm / 127.f : 1.f;
    if (lane == 0) g_sA[row] = sc;
    float isc = 1.f / sc;

    int8_t q1[4], q2[4];
    quant2(acc.x * isc, q1[0], q2[0]);
    quant2(acc.y * isc, q1[1], q2[1]);
    quant2(acc.z * isc, q1[2], q2[2]);
    quant2(acc.w * isc, q1[3], q2[3]);
    long o = (long)row * H + v;
    *(char4*)(g_Aq1 + o) = make_char4(q1[0], q1[1], q1[2], q1[3]);
    *(char4*)(g_Aq2 + o) = make_char4(q2[0], q2[1], q2[2], q2[3]);
}

// ---------------- quantize fp32 g_B rows -> g_Aq1/g_Aq2 + g_sA ----------------
__global__ void k_aquant(int N) {
    __shared__ float smax[256];
    int row = blockIdx.x;
    int t = threadIdx.x;
    float4 xv = ((const float4*)(g_B + (long)row * N))[t];
    float m = fmaxf(fmaxf(fabsf(xv.x), fabsf(xv.y)), fmaxf(fabsf(xv.z), fabsf(xv.w)));
    smax[t] = m;
    __syncthreads();
    for (int st = blockDim.x >> 1; st > 0; st >>= 1) {
        if (t < st) smax[t] = fmaxf(smax[t], smax[t + st]);
        __syncthreads();
    }
    float rm = smax[0];
    float sc = (rm > 0.f) ? rm / 127.f : 1.f;
    if (t == 0) g_sA[row] = sc;
    float isc = 1.f / sc;
    int8_t q1[4], q2[4];
    quant2(xv.x * isc, q1[0], q2[0]);
    quant2(xv.y * isc, q1[1], q2[1]);
    quant2(xv.z * isc, q1[2], q2[2]);
    quant2(xv.w * isc, q1[3], q2[3]);
    long o = (long)row * N + t * 4;
    *(char4*)(g_Aq1 + o) = make_char4(q1[0], q1[1], q1[2], q1[3]);
    *(char4*)(g_Aq2 + o) = make_char4(q2[0], q2[1], q2[2], q2[3]);
}

// ---------------- head final ----------------
__global__ void k_head_final(const float* __restrict__ W,
                             const float* __restrict__ b, float* __restrict__ out) {
    int warp = (blockIdx.x * blockDim.x + threadIdx.x) >> 5;
    int lane = threadIdx.x & 31;
    if (warp >= NN) return;
    const float* x = g_B + (long)warp * 512;
    float a0 = 0.f, a1 = 0.f, a2 = 0.f, a3 = 0.f;
    for (int k = lane; k < 512; k += 32) {
        float xv = x[k];
        float4 w = *(const float4*)(W + k * 4);
        a0 = fmaf(xv, w.x, a0);
        a1 = fmaf(xv, w.y, a1);
        a2 = fmaf(xv, w.z, a2);
        a3 = fmaf(xv, w.w, a3);
    }
#pragma unroll
    for (int off = 16; off > 0; off >>= 1) {
        a0 += __shfl_down_sync(0xffffffffu, a0, off);
        a1 += __shfl_down_sync(0xffffffffu, a1, off);
        a2 += __shfl_down_sync(0xffffffffu, a2, off);
        a3 += __shfl_down_sync(0xffffffffu, a3, off);
    }
    if (lane == 0) {
        out[warp * 4 + 0] = a0 + b[0];
        out[warp * 4 + 1] = a1 + b[1];
        out[warp * 4 + 2] = a2 + b[2];
        out[warp * 4 + 3] = a3 + b[3];
    }
}

// ---------------- host orchestration ----------------
#define IG_SMEM (2 * 30720)   // 61440

template <bool RELU, bool SCALED>
static void launch_ig(dim3 grid, int K, int N, int f32Sel, long woff, int soff,
                      const float* bias) {
    cudaFuncSetAttribute(igemm_kernel<RELU, SCALED>,
                         cudaFuncAttributeMaxDynamicSharedMemorySize, IG_SMEM);
    igemm_kernel<RELU, SCALED><<<grid, 256, IG_SMEM>>>(K, N, f32Sel, woff, soff, bias);
}

static void wprep(const float* W, int K, int N, long woff, int soff) {
    k_wmax<<<dim3((N + 255) / 256, 8), 256>>>(W, K, N, soff);
    k_wquant<<<dim3(N / 32, K / 32), dim3(32, 8)>>>(W, K, N, woff, soff);
}

extern "C" void kernel_launch(void* const* d_in, const int* in_sizes, int n_in,
                              void* d_out, int out_size) {
    const float* h_in = (const float*)d_in[0];
    const float* pos  = (const float*)d_in[1];
    const int*   ei   = (const int*)d_in[2];
    const float* l1_w1 = (const float*)d_in[3];
    const float* l1_b1 = (const float*)d_in[4];
    const float* l1_w2 = (const float*)d_in[5];
    const float* l1_b2 = (const float*)d_in[6];
    const float* l2_w1 = (const float*)d_in[7];
    const float* l2_b1 = (const float*)d_in[8];
    const float* l2_w2 = (const float*)d_in[9];
    const float* l2_b2 = (const float*)d_in[10];
    const float* l3_w1 = (const float*)d_in[11];
    const float* l3_b1 = (const float*)d_in[12];
    const float* l3_w2 = (const float*)d_in[13];
    const float* l3_b2 = (const float*)d_in[14];
    const float* l4_w1 = (const float*)d_in[15];
    const float* l4_b1 = (const float*)d_in[16];
    const float* l4_w2 = (const float*)d_in[17];
    const float* l4_b2 = (const float*)d_in[18];
    const float* hd_w1 = (const float*)d_in[19];
    const float* hd_b1 = (const float*)d_in[20];
    const float* hd_w2 = (const float*)d_in[21];
    const float* hd_b2 = (const float*)d_in[22];
    const float* hd_w3 = (const float*)d_in[23];
    const float* hd_b3 = (const float*)d_in[24];

    // prep: padded copy + CSR build
    k_copy_h<<<(NPAD * 16 / 4 + 255) / 256, 256>>>(h_in);
    k_count<<<(NE + 255) / 256, 256>>>(ei);
    k_scan<<<1, 1024>>>();
    k_scatter<<<(NE + 255) / 256, 256>>>(ei, pos);

    dim3 g1s(1, NPAD / 128);
    dim3 g128(1, NPAD / 64), g256(2, NPAD / 64), g1024(8, NPAD / 64), g512(4, NPAD / 64);

    // layer 1 front half (fp32)
    sgemm16_kernel<<<g1s, 256>>>(128, l1_w1, l1_b1);
    k_agg<128, 8><<<NPAD / 8, 256>>>(l1_w1 + 16 * 128);

    // weight quantization (transposed double-quant int8)
    wprep(l1_w2, 128, 128, OFF_L1W2, SOF_L1W2);
    wprep(l2_w1, 128, 256, OFF_L2W1, SOF_L2W1);
    wprep(l2_w2, 256, 256, OFF_L2W2, SOF_L2W2);
    wprep(l3_w1, 256, 1024, OFF_L3W1, SOF_L3W1);
    wprep(l3_w2, 1024, 1024, OFF_L3W2, SOF_L3W2);
    wprep(l4_w1, 1024, 1024, OFF_L4W1, SOF_L4W1);
    wprep(l4_w2, 1024, 1024, OFF_L4W2, SOF_L4W2);
    wprep(hd_w1, 1024, 1024, OFF_HDW1, SOF_HDW1);
    wprep(hd_w2, 1024, 512, OFF_HDW2, SOF_HDW2);

    // --- layer 1 back half ---
    launch_ig<true, true>(g128, 128, 128, 0, OFF_L1W2, SOF_L1W2, l1_b2);
    k_aquant<<<NPAD, 128 / 4>>>(128);

    // --- layer 2 ---
    launch_ig<false, false>(g256, 128, 256, 1, OFF_L2W1, SOF_L2W1, l2_b1);
    k_agg<256, 4><<<NPAD / 4, 256>>>(l2_w1 + 128 * 256);
    launch_ig<true, true>(g256, 256, 256, 0, OFF_L2W2, SOF_L2W2, l2_b2);
    k_aquant<<<NPAD, 256 / 4>>>(256);

    // --- layer 3 ---
    launch_ig<false, false>(g1024, 256, 1024, 1, OFF_L3W1, SOF_L3W1, l3_b1);
    k_agg<1024, 1><<<NPAD, 256>>>(l3_w1 + 256 * 1024);
    launch_ig<true, true>(g1024, 1024, 1024, 0, OFF_L3W2, SOF_L3W2, l3_b2);
    k_aquant<<<NPAD, 1024 / 4>>>(1024);

    // --- layer 4 ---
    launch_ig<false, false>(g1024, 1024, 1024, 1, OFF_L4W1, SOF_L4W1, l4_b1);
    k_agg<1024, 1><<<NPAD, 256>>>(l4_w1 + 1024 * 1024);
    launch_ig<true, true>(g1024, 1024, 1024, 0, OFF_L4W2, SOF_L4W2, l4_b2);
    k_aquant<<<NPAD, 1024 / 4>>>(1024);

    // --- head ---
    launch_ig<true, false>(g1024, 1024, 1024, 0, OFF_HDW1, SOF_HDW1, hd_b1);
    k_aquant<<<NPAD, 1024 / 4>>>(1024);
    launch_ig<true, false>(g512, 1024, 512, 0, OFF_HDW2, SOF_HDW2, hd_b2);
    k_head_final<<<(NN * 32 + 255) / 256, 256>>>(hd_w3, hd_b3, (float*)d_out);
}

// round 15
// speedup vs baseline: 1.1568x; 1.0332x over previous
#include <cuda_runtime.h>
#include <cstdint>

#define NN    20000
#define NPAD  20096   // 157 * 128
#define NE    320000

// ---------------- scratch (static device memory, no allocs) ----------------
__device__ float  g_H[(size_t)NPAD * 16];
__device__ float  g_A[(size_t)NPAD * 1024];   // GEMM1 outputs (fp32)
__device__ float  g_B[(size_t)NPAD * 1024];   // GEMM2/head outputs (fp32)
__device__ short  g_Xq[(size_t)NPAD * 1024];  // int16-compressed A (for agg gather)
__device__ float  g_sX[NPAD];                 // A row scales
__device__ int8_t g_Aq1[(size_t)NPAD * 1024]; // activation quant (main)
__device__ int8_t g_Aq2[(size_t)NPAD * 1024]; // activation quant (residual)
__device__ float  g_sA[NPAD];                 // activation row scales
__device__ int8_t g_Wq1[5095424];             // weight quant (main), [N,K] transposed
__device__ int8_t g_Wq2[5095424];             // weight quant (residual)
__device__ float  g_sW[6272];                 // weight row scales
__device__ float  g_sWmax[6272];              // weight row |max| (atomicMax accum)
// CSR by destination
__device__ int    g_icnt[NPAD];
__device__ int    g_off[NPAD + 1];
__device__ int    g_cur[NPAD];
__device__ int    g_srcs[NE];
__device__ float2 g_crel[NE];
__device__ float  g_inv[NPAD];
__device__ float  g_msk[NPAD];

#define OFF_L1W2 0L
#define OFF_L2W1 16384L
#define OFF_L2W2 49152L
#define OFF_L3W1 114688L
#define OFF_L3W2 376832L
#define OFF_L4W1 1425408L
#define OFF_L4W2 2473984L
#define OFF_HDW1 3522560L
#define OFF_HDW2 4571136L
#define SOF_L1W2 0
#define SOF_L2W1 128
#define SOF_L2W2 384
#define SOF_L3W1 640
#define SOF_L3W2 1664
#define SOF_L4W1 2688
#define SOF_L4W2 3712
#define SOF_HDW1 4736
#define SOF_HDW2 5760

struct WTab {
    const float* W[9];
    int K[9];
    int N[9];
    long woff[9];
    int soff[9];
};

__device__ __forceinline__ void quant2(float x, int8_t& q1, int8_t& q2) {
    float q1f = rintf(x);
    float r = x - q1f;
    float q2f = fminf(fmaxf(rintf(r * 254.f), -127.f), 127.f);
    q1 = (int8_t)(int)q1f;
    q2 = (int8_t)(int)q2f;
}

// ---------------- prep kernels ----------------
__global__ void k_copy_h(const float* __restrict__ src) {
    int i = blockIdx.x * blockDim.x + threadIdx.x;
    if (i < NPAD * 16 / 4) {
        float4 v = (i < NN * 16 / 4) ? ((const float4*)src)[i] : make_float4(0.f, 0.f, 0.f, 0.f);
        ((float4*)g_H)[i] = v;
    }
    if (i < NPAD) g_icnt[i] = 0;
    if (i < 6272) g_sWmax[i] = 0.f;
}

__global__ void k_count(const int* __restrict__ ei) {
    int e = blockIdx.x * blockDim.x + threadIdx.x;
    if (e < NE) atomicAdd(&g_icnt[ei[NE + e]], 1);
}

__global__ __launch_bounds__(1024) void k_scan() {
    __shared__ int sh[1024];
    __shared__ int carry;
    int tid = threadIdx.x;
    if (tid == 0) carry = 0;
    __syncthreads();
    for (int base = 0; base < NPAD; base += 1024) {
        int i = base + tid;
        int v = (i < NPAD) ? g_icnt[i] : 0;
        sh[tid] = v;
        __syncthreads();
#pragma unroll
        for (int off = 1; off < 1024; off <<= 1) {
            int t = (tid >= off) ? sh[tid - off] : 0;
            __syncthreads();
            if (tid >= off) sh[tid] += t;
            __syncthreads();
        }
        int incl = sh[tid];
        int c = carry;
        if (i < NPAD) {
            g_off[i] = c + incl - v;
            g_cur[i] = c + incl - v;
            float cf = (float)v;
            g_inv[i] = 1.0f / fmaxf(cf, 1.0f);
            g_msk[i] = (v > 0) ? 1.0f : 0.0f;
        }
        __syncthreads();
        if (tid == 1023) carry = c + incl;
        __syncthreads();
    }
    if (tid == 0) g_off[NPAD] = carry;
}

__global__ void k_scatter(const int* __restrict__ ei, const float* __restrict__ pos) {
    int e = blockIdx.x * blockDim.x + threadIdx.x;
    if (e < NE) {
        int s = ei[e];
        int d = ei[NE + e];
        int p = atomicAdd(&g_cur[d], 1);
        g_srcs[p] = s;
        float2 ps = ((const float2*)pos)[s];
        float2 pd = ((const float2*)pos)[d];
        g_crel[p] = make_float2(ps.x - pd.x, ps.y - pd.y);
    }
}

// ---------------- batched weight quantization ----------------
// grid (4, 8, 9): z = matrix, y = K-chunk, x*256+t = column n
__global__ void k_wmax_all(WTab tab) {
    int z = blockIdx.z;
    int N = tab.N[z], K = tab.K[z];
    int n = blockIdx.x * 256 + threadIdx.x;
    if (n >= N) return;
    const float* W = tab.W[z];
    int kchunk = K >> 3;
    int k0 = blockIdx.y * kchunk;
    float m = 0.f;
    for (int k = k0; k < k0 + kchunk; k++) m = fmaxf(m, fabsf(W[(long)k * N + n]));
    atomicMax((unsigned*)&g_sWmax[tab.soff[z] + n], __float_as_uint(m));
}

// grid (32, 32, 9): z = matrix; 32x32 fp tile transpose + double-quant
__global__ void k_wquant_all(WTab tab) {
    int z = blockIdx.z;
    int N = tab.N[z], K = tab.K[z];
    int bx = blockIdx.x, by = blockIdx.y;
    if (bx * 32 >= N || by * 32 >= K) return;
    const float* W = tab.W[z];
    long woff = tab.woff[z];
    int soff = tab.soff[z];
    __shared__ float tile[32][33];
    int tx = threadIdx.x, ty = threadIdx.y;  // block (32,8)
#pragma unroll
    for (int j = 0; j < 4; j++) {
        int k = by * 32 + ty + j * 8;
        int n = bx * 32 + tx;
        tile[ty + j * 8][tx] = W[(long)k * N + n];
    }
    __syncthreads();
#pragma unroll
    for (int j = 0; j < 4; j++) {
        int n = bx * 32 + ty + j * 8;
        int k = by * 32 + tx;
        float mx = g_sWmax[soff + n];
        float s = (mx > 0.f) ? mx / 127.f : 1.f;
        if (tx == 0) g_sW[soff + n] = s;
        float x = tile[tx][ty + j * 8] / s;
        int8_t q1, q2;
        quant2(x, q1, q2);
        g_Wq1[woff + (long)n * K + k] = q1;
        g_Wq2[woff + (long)n * K + k] = q2;
    }
}

// ---------------- mma helpers ----------------
__device__ __forceinline__ void ldsm4(uint32_t& r0, uint32_t& r1, uint32_t& r2, uint32_t& r3,
                                      const void* p) {
    uint32_t addr = (uint32_t)__cvta_generic_to_shared(p);
    asm volatile("ldmatrix.sync.aligned.m8n8.x4.shared.b16 {%0,%1,%2,%3}, [%4];\n"
                 : "=r"(r0), "=r"(r1), "=r"(r2), "=r"(r3) : "r"(addr));
}

__device__ __forceinline__ void imma(int* c, const uint32_t* a, uint32_t b0, uint32_t b1) {
    asm volatile(
        "mma.sync.aligned.m16n8k32.row.col.s32.s8.s8.s32 "
        "{%0,%1,%2,%3}, {%4,%5,%6,%7}, {%8,%9}, {%0,%1,%2,%3};\n"
        : "+r"(c[0]), "+r"(c[1]), "+r"(c[2]), "+r"(c[3])
        : "r"(a[0]), "r"(a[1]), "r"(a[2]), "r"(a[3]), "r"(b0), "r"(b1));
}

__device__ __forceinline__ void cpasync16(uint32_t saddr, const void* gptr) {
    asm volatile("cp.async.cg.shared.global [%0], [%1], 16;\n" :: "r"(saddr), "l"(gptr));
}

// ---------------- int8 tensor-core GEMM (R12-proven): 64x128 tile, 256 thr, 2 CTAs/SM, 2-stage ----------------
template <bool RELU, bool SCALED>
__global__ __launch_bounds__(256, 2) void igemm_kernel(
    int K, int N, int f32Sel, long woff, int soff, const float* __restrict__ bias)
{
    constexpr int BK = 64;
    constexpr int PITCH = 80;
    constexpr int APLANE = 64 * PITCH;
    constexpr int BPLANE = 128 * PITCH;
    constexpr int STAGE = 2 * APLANE + 2 * BPLANE;  // 30720
    extern __shared__ __align__(16) char smem[];
    const uint32_t sbase = (uint32_t)__cvta_generic_to_shared(smem);

    const int8_t* Wq1 = g_Wq1 + woff;
    const int8_t* Wq2 = g_Wq2 + woff;

    const int bm = blockIdx.y * 64;
    const int bn = blockIdx.x * 128;
    const int tid  = threadIdx.x;
    const int warp = tid >> 5;
    const int lane = tid & 31;
    const int warp_m = warp >> 2;
    const int warp_n = warp & 3;

    int accM[2][4][4], accC[2][4][4];
#pragma unroll
    for (int i = 0; i < 2; i++)
#pragma unroll
        for (int j = 0; j < 4; j++)
#pragma unroll
            for (int r = 0; r < 4; r++) { accM[i][j][r] = 0; accC[i][j][r] = 0; }

    const int a_row = lane & 15;
    const int a_koffB = ((lane >> 4) << 4);
    const int b_row = (lane & 7) + ((lane & 16) >> 1);
    const int b_koffB = (lane & 8) * 2;

    const int nChunk = K / BK;

    auto issue = [&](int stage, int k0) {
        uint32_t sb = sbase + stage * STAGE;
        {
            int row = tid >> 2;
            int seg = tid & 3;
            uint32_t so = sb + row * PITCH + seg * 16;
            long aoff = (long)(bm + row) * K + k0 + seg * 16;
            cpasync16(so,          g_Aq1 + aoff);
            cpasync16(so + APLANE, g_Aq2 + aoff);
        }
#pragma unroll
        for (int i = 0; i < 2; i++) {
            int idx = tid + i * 256;
            int row = idx >> 2;
            int seg = idx & 3;
            uint32_t so = sb + 2 * APLANE + row * PITCH + seg * 16;
            long boff = (long)(bn + row) * K + k0 + seg * 16;
            cpasync16(so,          Wq1 + boff);
            cpasync16(so + BPLANE, Wq2 + boff);
        }
        asm volatile("cp.async.commit_group;\n" ::: "memory");
    };

    issue(0, 0);
    if (nChunk > 1) issue(1, BK);

    for (int c = 0; c < nChunk; c++) {
        int s = c & 1;
        if (c + 1 < nChunk)
            asm volatile("cp.async.wait_group 1;\n" ::: "memory");
        else
            asm volatile("cp.async.wait_group 0;\n" ::: "memory");
        __syncthreads();

        char* sA1 = smem + s * STAGE;
        char* sA2 = sA1 + APLANE;
        char* sB1 = sA1 + 2 * APLANE;
        char* sB2 = sB1 + BPLANE;

#pragma unroll
        for (int ksB = 0; ksB < 64; ksB += 32) {
            uint32_t aq1[2][4], aq2[2][4];
#pragma unroll
            for (int mt = 0; mt < 2; mt++) {
                int m0 = warp_m * 32 + mt * 16;
                ldsm4(aq1[mt][0], aq1[mt][1], aq1[mt][2], aq1[mt][3],
                      sA1 + (m0 + a_row) * PITCH + ksB + a_koffB);
                ldsm4(aq2[mt][0], aq2[mt][1], aq2[mt][2], aq2[mt][3],
                      sA2 + (m0 + a_row) * PITCH + ksB + a_koffB);
            }
#pragma unroll
            for (int pair = 0; pair < 2; pair++) {
                int n0 = warp_n * 32 + pair * 16;
                uint32_t b1_0, b1_1, b1_2, b1_3, b2_0, b2_1, b2_2, b2_3;
                ldsm4(b1_0, b1_1, b1_2, b1_3, sB1 + (n0 + b_row) * PITCH + ksB + b_koffB);
                ldsm4(b2_0, b2_1, b2_2, b2_3, sB2 + (n0 + b_row) * PITCH + ksB + b_koffB);
#pragma unroll
                for (int mt = 0; mt < 2; mt++) {
                    int* m0p = accM[mt][pair * 2 + 0];
                    int* c0p = accC[mt][pair * 2 + 0];
                    int* m1p = accM[mt][pair * 2 + 1];
                    int* c1p = accC[mt][pair * 2 + 1];
                    imma(m0p, aq1[mt], b1_0, b1_1);
                    imma(c0p, aq1[mt], b2_0, b2_1);
                    imma(c0p, aq2[mt], b1_0, b1_1);
                    imma(m1p, aq1[mt], b1_2, b1_3);
                    imma(c1p, aq1[mt], b2_2, b2_3);
                    imma(c1p, aq2[mt], b1_2, b1_3);
                }
            }
        }
        __syncthreads();

        if (c + 2 < nChunk) issue(s, (c + 2) * BK);
    }

    float* Cf = (f32Sel == 1) ? g_A : g_B;
    const int rbase = bm + warp_m * 32 + (lane >> 2);
    const int cbase = bn + warp_n * 32 + 2 * (lane & 3);
    constexpr float INV254 = 1.f / 254.f;
#pragma unroll
    for (int mt = 0; mt < 2; mt++) {
#pragma unroll
        for (int half = 0; half < 2; half++) {
            int r = rbase + mt * 16 + half * 8;
            float sa = g_sA[r];
            float bmsk = SCALED ? g_msk[r] : 1.0f;
#pragma unroll
            for (int p = 0; p < 4; p++) {
                int c = cbase + p * 8;
                float2 sw = *(const float2*)(g_sW + soff + c);
                float2 bv = *(const float2*)(bias + c);
                float d0 = (float)accM[mt][p][half * 2 + 0]
                         + (float)accC[mt][p][half * 2 + 0] * INV254;
                float d1 = (float)accM[mt][p][half * 2 + 1]
                         + (float)accC[mt][p][half * 2 + 1] * INV254;
                float v0 = sa * sw.x * d0 + bv.x * bmsk;
                float v1 = sa * sw.y * d1 + bv.y * bmsk;
                if (RELU) { v0 = fmaxf(v0, 0.f); v1 = fmaxf(v1, 0.f); }
                *(float2*)(Cf + (long)r * N + c) = make_float2(v0, v1);
            }
        }
    }
}

// ---------------- SIMT SGEMM for K=16 first layer (g_H -> g_A) ----------------
__global__ __launch_bounds__(256) void sgemm16_kernel(
    int N, const float* __restrict__ B, const float* __restrict__ bias)
{
    constexpr int BM = 128, BK = 16, TM = 8, TN = 8;
    __shared__ __align__(16) float As[BK][BM];
    __shared__ __align__(16) float Bs[BK][128];
    const int bm = blockIdx.y * BM;
    const int bn = blockIdx.x * 128;
    const int tid = threadIdx.x;
    const int arow = tid >> 2, acol = (tid & 3) << 2;
    const int brow = tid >> 5, bcol = (tid & 31) << 2;
    const int ty = (tid >> 4) * TM, tx = (tid & 15) * TN;
    float acc[TM][TN];
#pragma unroll
    for (int i = 0; i < TM; i++)
#pragma unroll
        for (int j = 0; j < TN; j++) acc[i][j] = 0.f;
    const int K = 16;
#pragma unroll
    for (int i = 0; i < 2; i++) {
        int r = arow + i * 64;
        float4 v = *(const float4*)(g_H + (long)(bm + r) * K + acol);
        As[acol + 0][r] = v.x; As[acol + 1][r] = v.y;
        As[acol + 2][r] = v.z; As[acol + 3][r] = v.w;
    }
#pragma unroll
    for (int i = 0; i < 2; i++) {
        int r = brow + i * 8;
        *(float4*)(&Bs[r][bcol]) = *(const float4*)(B + (long)r * N + bn + bcol);
    }
    __syncthreads();
#pragma unroll
    for (int kk = 0; kk < BK; kk++) {
        float ra[TM], rb[TN];
        *(float4*)(ra)     = *(const float4*)(&As[kk][ty]);
        *(float4*)(ra + 4) = *(const float4*)(&As[kk][ty + 4]);
        *(float4*)(rb)     = *(const float4*)(&Bs[kk][tx]);
        *(float4*)(rb + 4) = *(const float4*)(&Bs[kk][tx + 4]);
#pragma unroll
        for (int i = 0; i < TM; i++)
#pragma unroll
            for (int j = 0; j < TN; j++) acc[i][j] += ra[i] * rb[j];
    }
#pragma unroll
    for (int i = 0; i < TM; i++) {
        long m = bm + ty + i;
        float* crow = g_A + m * N + bn + tx;
#pragma unroll
        for (int j = 0; j < TN; j += 4) {
            float4 bv = *(const float4*)(bias + bn + tx + j);
            float4 o;
            o.x = acc[i][j + 0] + bv.x; o.y = acc[i][j + 1] + bv.y;
            o.z = acc[i][j + 2] + bv.z; o.w = acc[i][j + 3] + bv.w;
            *(float4*)(crow + j) = o;
        }
    }
}

// ---------------- compress g_A rows -> int16 plane g_Xq + row scale g_sX ----------------
// grid NPAD, block N/4 (32..256)
__global__ void k_aqX(int N) {
    __shared__ float smax[256];
    int row = blockIdx.x;
    int t = threadIdx.x;
    float4 xv = ((const float4*)(g_A + (long)row * N))[t];
    float m = fmaxf(fmaxf(fabsf(xv.x), fabsf(xv.y)), fmaxf(fabsf(xv.z), fabsf(xv.w)));
    smax[t] = m;
    __syncthreads();
    for (int st = blockDim.x >> 1; st > 0; st >>= 1) {
        if (t < st) smax[t] = fmaxf(smax[t], smax[t + st]);
        __syncthreads();
    }
    float rm = smax[0];
    float sc = (rm > 0.f) ? rm / 127.f : 1.f;
    if (t == 0) g_sX[row] = sc;
    float f = 254.f / sc;
    short4 q;
    q.x = (short)(int)rintf(xv.x * f);
    q.y = (short)(int)rintf(xv.y * f);
    q.z = (short)(int)rintf(xv.z * f);
    q.w = (short)(int)rintf(xv.w * f);
    ((short4*)(g_Xq + (long)row * N))[t] = q;
}

// ---------------- CSR aggregation, int16-compressed gather, fused output double-quant ----------------
template <int H, int RPB>
__global__ __launch_bounds__(256) void k_agg(const float* __restrict__ w1p) {
    constexpr int TPR = H / 4;
    static_assert(TPR * RPB == 256, "block mapping");
    __shared__ __align__(16) float sw0[H];
    __shared__ __align__(16) float sw1[H];
    __shared__ float smax[256];
    for (int i = threadIdx.x; i < H; i += 256) {
        sw0[i] = w1p[i];
        sw1[i] = w1p[H + i];
    }
    __syncthreads();

    const int lr   = threadIdx.x / TPR;
    const int lane = threadIdx.x % TPR;
    const int row  = blockIdx.x * RPB + lr;
    const int v    = lane * 4;

    const float4 w0 = *(const float4*)(sw0 + v);
    const float4 w1 = *(const float4*)(sw1 + v);

    const int beg = g_off[row];
    const int end = g_off[row + 1];
    constexpr float INV254 = 1.f / 254.f;

    float4 acc = make_float4(0.f, 0.f, 0.f, 0.f);
    int j = beg;
    for (; j + 2 <= end; j += 2) {
        int s0 = __ldg(g_srcs + j);
        int s1 = __ldg(g_srcs + j + 1);
        float2 r0 = __ldg(g_crel + j);
        float2 r1 = __ldg(g_crel + j + 1);
        float f0 = __ldg(g_sX + s0) * INV254;
        float f1 = __ldg(g_sX + s1) * INV254;
        int2 q0 = __ldg((const int2*)(g_Xq + (long)s0 * H) + lane);
        int2 q1 = __ldg((const int2*)(g_Xq + (long)s1 * H) + lane);
        float a0x = (float)((short)q0.x) * f0, a0y = (float)(q0.x >> 16) * f0;
        float a0z = (float)((short)q0.y) * f0, a0w = (float)(q0.y >> 16) * f0;
        float a1x = (float)((short)q1.x) * f1, a1y = (float)(q1.x >> 16) * f1;
        float a1z = (float)((short)q1.y) * f1, a1w = (float)(q1.y >> 16) * f1;
        acc.x += fmaxf(fmaf(r0.x, w0.x, fmaf(r0.y, w1.x, a0x)), 0.f);
        acc.y += fmaxf(fmaf(r0.x, w0.y, fmaf(r0.y, w1.y, a0y)), 0.f);
        acc.z += fmaxf(fmaf(r0.x, w0.z, fmaf(r0.y, w1.z, a0z)), 0.f);
        acc.w += fmaxf(fmaf(r0.x, w0.w, fmaf(r0.y, w1.w, a0w)), 0.f);
        acc.x += fmaxf(fmaf(r1.x, w0.x, fmaf(r1.y, w1.x, a1x)), 0.f);
        acc.y += fmaxf(fmaf(r1.x, w0.y, fmaf(r1.y, w1.y, a1y)), 0.f);
        acc.z += fmaxf(fmaf(r1.x, w0.z, fmaf(r1.y, w1.z, a1z)), 0.f);
        acc.w += fmaxf(fmaf(r1.x, w0.w, fmaf(r1.y, w1.w, a1w)), 0.f);
    }
    if (j < end) {
        int s0 = __ldg(g_srcs + j);
        float2 r0 = __ldg(g_crel + j);
        float f0 = __ldg(g_sX + s0) * INV254;
        int2 q0 = __ldg((const int2*)(g_Xq + (long)s0 * H) + lane);
        float a0x = (float)((short)q0.x) * f0, a0y = (float)(q0.x >> 16) * f0;
        float a0z = (float)((short)q0.y) * f0, a0w = (float)(q0.y >> 16) * f0;
        acc.x += fmaxf(fmaf(r0.x, w0.x, fmaf(r0.y, w1.x, a0x)), 0.f);
        acc.y += fmaxf(fmaf(r0.x, w0.y, fmaf(r0.y, w1.y, a0y)), 0.f);
        acc.z += fmaxf(fmaf(r0.x, w0.z, fmaf(r0.y, w1.z, a0z)), 0.f);
        acc.w += fmaxf(fmaf(r0.x, w0.w, fmaf(r0.y, w1.w, a0w)), 0.f);
    }
    float s = g_inv[row];
    acc.x *= s; acc.y *= s; acc.z *= s; acc.w *= s;

    smax[threadIdx.x] = fmaxf(fmaxf(acc.x, acc.y), fmaxf(acc.z, acc.w));
    __syncthreads();
    const int gb = lr * TPR;
#pragma unroll
    for (int st = TPR >> 1; st > 0; st >>= 1) {
        if (lane < st) smax[gb + lane] = fmaxf(smax[gb + lane], smax[gb + lane + st]);
        __syncthreads();
    }
    float rm = smax[gb];
    float sc = (rm > 0.f) ? rm / 127.f : 1.f;
    if (lane == 0) g_sA[row] = sc;
    float isc = 1.f / sc;

    int8_t q1[4], q2[4];
    quant2(acc.x * isc, q1[0], q2[0]);
    quant2(acc.y * isc, q1[1], q2[1]);
    quant2(acc.z * isc, q1[2], q2[2]);
    quant2(acc.w * isc, q1[3], q2[3]);
    long o = (long)row * H + v;
    *(char4*)(g_Aq1 + o) = make_char4(q1[0], q1[1], q1[2], q1[3]);
    *(char4*)(g_Aq2 + o) = make_char4(q2[0], q2[1], q2[2], q2[3]);
}

// ---------------- quantize fp32 g_B rows -> g_Aq1/g_Aq2 + g_sA ----------------
__global__ void k_aquant(int N) {
    __shared__ float smax[256];
    int row = blockIdx.x;
    int t = threadIdx.x;
    float4 xv = ((const float4*)(g_B + (long)row * N))[t];
    float m = fmaxf(fmaxf(fabsf(xv.x), fabsf(xv.y)), fmaxf(fabsf(xv.z), fabsf(xv.w)));
    smax[t] = m;
    __syncthreads();
    for (int st = blockDim.x >> 1; st > 0; st >>= 1) {
        if (t < st) smax[t] = fmaxf(smax[t], smax[t + st]);
        __syncthreads();
    }
    float rm = smax[0];
    float sc = (rm > 0.f) ? rm / 127.f : 1.f;
    if (t == 0) g_sA[row] = sc;
    float isc = 1.f / sc;
    int8_t q1[4], q2[4];
    quant2(xv.x * isc, q1[0], q2[0]);
    quant2(xv.y * isc, q1[1], q2[1]);
    quant2(xv.z * isc, q1[2], q2[2]);
    quant2(xv.w * isc, q1[3], q2[3]);
    long o = (long)row * N + t * 4;
    *(char4*)(g_Aq1 + o) = make_char4(q1[0], q1[1], q1[2], q1[3]);
    *(char4*)(g_Aq2 + o) = make_char4(q2[0], q2[1], q2[2], q2[3]);
}

// ---------------- head final ----------------
__global__ void k_head_final(const float* __restrict__ W,
                             const float* __restrict__ b, float* __restrict__ out) {
    int warp = (blockIdx.x * blockDim.x + threadIdx.x) >> 5;
    int lane = threadIdx.x & 31;
    if (warp >= NN) return;
    const float* x = g_B + (long)warp * 512;
    float a0 = 0.f, a1 = 0.f, a2 = 0.f, a3 = 0.f;
    for (int k = lane; k < 512; k += 32) {
        float xv = x[k];
        float4 w = *(const float4*)(W + k * 4);
        a0 = fmaf(xv, w.x, a0);
        a1 = fmaf(xv, w.y, a1);
        a2 = fmaf(xv, w.z, a2);
        a3 = fmaf(xv, w.w, a3);
    }
#pragma unroll
    for (int off = 16; off > 0; off >>= 1) {
        a0 += __shfl_down_sync(0xffffffffu, a0, off);
        a1 += __shfl_down_sync(0xffffffffu, a1, off);
        a2 += __shfl_down_sync(0xffffffffu, a2, off);
        a3 += __shfl_down_sync(0xffffffffu, a3, off);
    }
    if (lane == 0) {
        out[warp * 4 + 0] = a0 + b[0];
        out[warp * 4 + 1] = a1 + b[1];
        out[warp * 4 + 2] = a2 + b[2];
        out[warp * 4 + 3] = a3 + b[3];
    }
}

// ---------------- host orchestration ----------------
#define IG_SMEM (2 * 30720)   // 61440

template <bool RELU, bool SCALED>
static void launch_ig(dim3 grid, int K, int N, int f32Sel, long woff, int soff,
                      const float* bias) {
    cudaFuncSetAttribute(igemm_kernel<RELU, SCALED>,
                         cudaFuncAttributeMaxDynamicSharedMemorySize, IG_SMEM);
    igemm_kernel<RELU, SCALED><<<grid, 256, IG_SMEM>>>(K, N, f32Sel, woff, soff, bias);
}

extern "C" void kernel_launch(void* const* d_in, const int* in_sizes, int n_in,
                              void* d_out, int out_size) {
    const float* h_in = (const float*)d_in[0];
    const float* pos  = (const float*)d_in[1];
    const int*   ei   = (const int*)d_in[2];
    const float* l1_w1 = (const float*)d_in[3];
    const float* l1_b1 = (const float*)d_in[4];
    const float* l1_w2 = (const float*)d_in[5];
    const float* l1_b2 = (const float*)d_in[6];
    const float* l2_w1 = (const float*)d_in[7];
    const float* l2_b1 = (const float*)d_in[8];
    const float* l2_w2 = (const float*)d_in[9];
    const float* l2_b2 = (const float*)d_in[10];
    const float* l3_w1 = (const float*)d_in[11];
    const float* l3_b1 = (const float*)d_in[12];
    const float* l3_w2 = (const float*)d_in[13];
    const float* l3_b2 = (const float*)d_in[14];
    const float* l4_w1 = (const float*)d_in[15];
    const float* l4_b1 = (const float*)d_in[16];
    const float* l4_w2 = (const float*)d_in[17];
    const float* l4_b2 = (const float*)d_in[18];
    const float* hd_w1 = (const float*)d_in[19];
    const float* hd_b1 = (const float*)d_in[20];
    const float* hd_w2 = (const float*)d_in[21];
    const float* hd_b2 = (const float*)d_in[22];
    const float* hd_w3 = (const float*)d_in[23];
    const float* hd_b3 = (const float*)d_in[24];

    // prep: padded copy + CSR build
    k_copy_h<<<(NPAD * 16 / 4 + 255) / 256, 256>>>(h_in);
    k_count<<<(NE + 255) / 256, 256>>>(ei);
    k_scan<<<1, 1024>>>();
    k_scatter<<<(NE + 255) / 256, 256>>>(ei, pos);

    // batched weight quantization (2 launches for all 9 matrices)
    WTab tab;
    const float* Ws[9] = {l1_w2, l2_w1, l2_w2, l3_w1, l3_w2, l4_w1, l4_w2, hd_w1, hd_w2};
    int Ks[9] = {128, 128, 256, 256, 1024, 1024, 1024, 1024, 1024};
    int Ns[9] = {128, 256, 256, 1024, 1024, 1024, 1024, 1024, 512};
    long wof[9] = {OFF_L1W2, OFF_L2W1, OFF_L2W2, OFF_L3W1, OFF_L3W2,
                   OFF_L4W1, OFF_L4W2, OFF_HDW1, OFF_HDW2};
    int sof[9] = {SOF_L1W2, SOF_L2W1, SOF_L2W2, SOF_L3W1, SOF_L3W2,
                  SOF_L4W1, SOF_L4W2, SOF_HDW1, SOF_HDW2};
    for (int i = 0; i < 9; i++) {
        tab.W[i] = Ws[i]; tab.K[i] = Ks[i]; tab.N[i] = Ns[i];
        tab.woff[i] = wof[i]; tab.soff[i] = sof[i];
    }
    k_wmax_all<<<dim3(4, 8, 9), 256>>>(tab);
    k_wquant_all<<<dim3(32, 32, 9), dim3(32, 8)>>>(tab);

    dim3 g1s(1, NPAD / 128);
    dim3 g128(1, NPAD / 64), g256(2, NPAD / 64), g1024(8, NPAD / 64), g512(4, NPAD / 64);

    // --- layer 1: 16 -> 128 -> 128 ---
    sgemm16_kernel<<<g1s, 256>>>(128, l1_w1, l1_b1);
    k_aqX<<<NPAD, 128 / 4>>>(128);
    k_agg<128, 8><<<NPAD / 8, 256>>>(l1_w1 + 16 * 128);
    launch_ig<true, true>(g128, 128, 128, 0, OFF_L1W2, SOF_L1W2, l1_b2);
    k_aquant<<<NPAD, 128 / 4>>>(128);

    // --- layer 2 ---
    launch_ig<false, false>(g256, 128, 256, 1, OFF_L2W1, SOF_L2W1, l2_b1);
    k_aqX<<<NPAD, 256 / 4>>>(256);
    k_agg<256, 4><<<NPAD / 4, 256>>>(l2_w1 + 128 * 256);
    launch_ig<true, true>(g256, 256, 256, 0, OFF_L2W2, SOF_L2W2, l2_b2);
    k_aquant<<<NPAD, 256 / 4>>>(256);

    // --- layer 3 ---
    launch_ig<false, false>(g1024, 256, 1024, 1, OFF_L3W1, SOF_L3W1, l3_b1);
    k_aqX<<<NPAD, 1024 / 4>>>(1024);
    k_agg<1024, 1><<<NPAD, 256>>>(l3_w1 + 256 * 1024);
    launch_ig<true, true>(g1024, 1024, 1024, 0, OFF_L3W2, SOF_L3W2, l3_b2);
    k_aquant<<<NPAD, 1024 / 4>>>(1024);

    // --- layer 4 ---
    launch_ig<false, false>(g1024, 1024, 1024, 1, OFF_L4W1, SOF_L4W1, l4_b1);
    k_aqX<<<NPAD, 1024 / 4>>>(1024);
    k_agg<1024, 1><<<NPAD, 256>>>(l4_w1 + 1024 * 1024);
    launch_ig<true, true>(g1024, 1024, 1024, 0, OFF_L4W2, SOF_L4W2, l4_b2);
    k_aquant<<<NPAD, 1024 / 4>>>(1024);

    // --- head ---
    launch_ig<true, false>(g1024, 1024, 1024, 0, OFF_HDW1, SOF_HDW1, hd_b1);
    k_aquant<<<NPAD, 1024 / 4>>>(1024);
    launch_ig<true, false>(g512, 1024, 512, 0, OFF_HDW2, SOF_HDW2, hd_b2);
    k_head_final<<<(NN * 32 + 255) / 256, 256>>>(hd_w3, hd_b3, (float*)d_out);
}

// round 16
// speedup vs baseline: 1.1963x; 1.0342x over previous
#include <cuda_runtime.h>
#include <cstdint>

#define NN    20000
#define NPAD  20096   // 157 * 128
#define NE    320000

// ---------------- scratch (static device memory, no allocs) ----------------
__device__ float  g_H[(size_t)NPAD * 16];
__device__ float  g_A[(size_t)NPAD * 1024];   // sgemm16 output (layer-1 only) + hd2 unused
__device__ float  g_B[(size_t)NPAD * 1024];   // hd2 output (fp32, read by head_final)
__device__ short  g_Xq[(size_t)NPAD * 1024];  // int16 activations (block-scaled)
__device__ float  g_bs[(size_t)NPAD * 8];     // per-(row, 128-col block) scales
__device__ int8_t g_Aq1[(size_t)NPAD * 1024]; // activation quant (main)
__device__ int8_t g_Aq2[(size_t)NPAD * 1024]; // activation quant (residual)
__device__ float  g_sA[NPAD];                 // activation row scales
__device__ int8_t g_Wq1[5095424];             // weight quant (main), [N,K] transposed
__device__ int8_t g_Wq2[5095424];             // weight quant (residual)
__device__ float  g_sW[6272];                 // weight row scales
__device__ float  g_sWmax[6272];              // weight row |max| (atomicMax accum)
// CSR by destination
__device__ int    g_icnt[NPAD];
__device__ int    g_off[NPAD + 1];
__device__ int    g_cur[NPAD];
__device__ int    g_srcs[NE];
__device__ float2 g_crel[NE];
__device__ float  g_inv[NPAD];
__device__ float  g_msk[NPAD];

#define OFF_L1W2 0L
#define OFF_L2W1 16384L
#define OFF_L2W2 49152L
#define OFF_L3W1 114688L
#define OFF_L3W2 376832L
#define OFF_L4W1 1425408L
#define OFF_L4W2 2473984L
#define OFF_HDW1 3522560L
#define OFF_HDW2 4571136L
#define SOF_L1W2 0
#define SOF_L2W1 128
#define SOF_L2W2 384
#define SOF_L3W1 640
#define SOF_L3W2 1664
#define SOF_L4W1 2688
#define SOF_L4W2 3712
#define SOF_HDW1 4736
#define SOF_HDW2 5760

struct WTab {
    const float* W[9];
    int K[9];
    int N[9];
    long woff[9];
    int soff[9];
};

__device__ __forceinline__ void quant2(float x, int8_t& q1, int8_t& q2) {
    float q1f = rintf(x);
    float r = x - q1f;
    float q2f = fminf(fmaxf(rintf(r * 254.f), -127.f), 127.f);
    q1 = (int8_t)(int)q1f;
    q2 = (int8_t)(int)q2f;
}

// ---------------- prep kernels ----------------
__global__ void k_copy_h(const float* __restrict__ src) {
    int i = blockIdx.x * blockDim.x + threadIdx.x;
    if (i < NPAD * 16 / 4) {
        float4 v = (i < NN * 16 / 4) ? ((const float4*)src)[i] : make_float4(0.f, 0.f, 0.f, 0.f);
        ((float4*)g_H)[i] = v;
    }
    if (i < NPAD) g_icnt[i] = 0;
    if (i < 6272) g_sWmax[i] = 0.f;
}

__global__ void k_count(const int* __restrict__ ei) {
    int e = blockIdx.x * blockDim.x + threadIdx.x;
    if (e < NE) atomicAdd(&g_icnt[ei[NE + e]], 1);
}

__global__ __launch_bounds__(1024) void k_scan() {
    __shared__ int sh[1024];
    __shared__ int carry;
    int tid = threadIdx.x;
    if (tid == 0) carry = 0;
    __syncthreads();
    for (int base = 0; base < NPAD; base += 1024) {
        int i = base + tid;
        int v = (i < NPAD) ? g_icnt[i] : 0;
        sh[tid] = v;
        __syncthreads();
#pragma unroll
        for (int off = 1; off < 1024; off <<= 1) {
            int t = (tid >= off) ? sh[tid - off] : 0;
            __syncthreads();
            if (tid >= off) sh[tid] += t;
            __syncthreads();
        }
        int incl = sh[tid];
        int c = carry;
        if (i < NPAD) {
            g_off[i] = c + incl - v;
            g_cur[i] = c + incl - v;
            float cf = (float)v;
            g_inv[i] = 1.0f / fmaxf(cf, 1.0f);
            g_msk[i] = (v > 0) ? 1.0f : 0.0f;
        }
        __syncthreads();
        if (tid == 1023) carry = c + incl;
        __syncthreads();
    }
    if (tid == 0) g_off[NPAD] = carry;
}

__global__ void k_scatter(const int* __restrict__ ei, const float* __restrict__ pos) {
    int e = blockIdx.x * blockDim.x + threadIdx.x;
    if (e < NE) {
        int s = ei[e];
        int d = ei[NE + e];
        int p = atomicAdd(&g_cur[d], 1);
        g_srcs[p] = s;
        float2 ps = ((const float2*)pos)[s];
        float2 pd = ((const float2*)pos)[d];
        g_crel[p] = make_float2(ps.x - pd.x, ps.y - pd.y);
    }
}

// ---------------- batched weight quantization ----------------
__global__ void k_wmax_all(WTab tab) {
    int z = blockIdx.z;
    int N = tab.N[z], K = tab.K[z];
    int n = blockIdx.x * 256 + threadIdx.x;
    if (n >= N) return;
    const float* W = tab.W[z];
    int kchunk = K >> 3;
    int k0 = blockIdx.y * kchunk;
    float m = 0.f;
    for (int k = k0; k < k0 + kchunk; k++) m = fmaxf(m, fabsf(W[(long)k * N + n]));
    atomicMax((unsigned*)&g_sWmax[tab.soff[z] + n], __float_as_uint(m));
}

__global__ void k_wquant_all(WTab tab) {
    int z = blockIdx.z;
    int N = tab.N[z], K = tab.K[z];
    int bx = blockIdx.x, by = blockIdx.y;
    if (bx * 32 >= N || by * 32 >= K) return;
    const float* W = tab.W[z];
    long woff = tab.woff[z];
    int soff = tab.soff[z];
    __shared__ float tile[32][33];
    int tx = threadIdx.x, ty = threadIdx.y;  // block (32,8)
#pragma unroll
    for (int j = 0; j < 4; j++) {
        int k = by * 32 + ty + j * 8;
        int n = bx * 32 + tx;
        tile[ty + j * 8][tx] = W[(long)k * N + n];
    }
    __syncthreads();
#pragma unroll
    for (int j = 0; j < 4; j++) {
        int n = bx * 32 + ty + j * 8;
        int k = by * 32 + tx;
        float mx = g_sWmax[soff + n];
        float s = (mx > 0.f) ? mx / 127.f : 1.f;
        if (tx == 0) g_sW[soff + n] = s;
        float x = tile[tx][ty + j * 8] / s;
        int8_t q1, q2;
        quant2(x, q1, q2);
        g_Wq1[woff + (long)n * K + k] = q1;
        g_Wq2[woff + (long)n * K + k] = q2;
    }
}

// ---------------- mma helpers ----------------
__device__ __forceinline__ void ldsm4(uint32_t& r0, uint32_t& r1, uint32_t& r2, uint32_t& r3,
                                      const void* p) {
    uint32_t addr = (uint32_t)__cvta_generic_to_shared(p);
    asm volatile("ldmatrix.sync.aligned.m8n8.x4.shared.b16 {%0,%1,%2,%3}, [%4];\n"
                 : "=r"(r0), "=r"(r1), "=r"(r2), "=r"(r3) : "r"(addr));
}

__device__ __forceinline__ void imma(int* c, const uint32_t* a, uint32_t b0, uint32_t b1) {
    asm volatile(
        "mma.sync.aligned.m16n8k32.row.col.s32.s8.s8.s32 "
        "{%0,%1,%2,%3}, {%4,%5,%6,%7}, {%8,%9}, {%0,%1,%2,%3};\n"
        : "+r"(c[0]), "+r"(c[1]), "+r"(c[2]), "+r"(c[3])
        : "r"(a[0]), "r"(a[1]), "r"(a[2]), "r"(a[3]), "r"(b0), "r"(b1));
}

__device__ __forceinline__ void cpasync16(uint32_t saddr, const void* gptr) {
    asm volatile("cp.async.cg.shared.global [%0], [%1], 16;\n" :: "r"(saddr), "l"(gptr));
}

// ---------------- int8 tensor-core GEMM: 64x128 tile, 256 thr, 2 CTAs/SM, 2-stage ----------------
// OUTX=true: write int16 g_Xq + per-(row,ntile) block scale g_bs. OUTX=false: fp32 -> g_B.
template <bool RELU, bool SCALED, bool OUTX>
__global__ __launch_bounds__(256, 2) void igemm_kernel(
    int K, int N, long woff, int soff, const float* __restrict__ bias)
{
    constexpr int BK = 64;
    constexpr int PITCH = 80;
    constexpr int APLANE = 64 * PITCH;
    constexpr int BPLANE = 128 * PITCH;
    constexpr int STAGE = 2 * APLANE + 2 * BPLANE;  // 30720
    extern __shared__ __align__(16) char smem[];
    const uint32_t sbase = (uint32_t)__cvta_generic_to_shared(smem);

    const int8_t* Wq1 = g_Wq1 + woff;
    const int8_t* Wq2 = g_Wq2 + woff;

    const int bm = blockIdx.y * 64;
    const int bn = blockIdx.x * 128;
    const int tid  = threadIdx.x;
    const int warp = tid >> 5;
    const int lane = tid & 31;
    const int warp_m = warp >> 2;
    const int warp_n = warp & 3;

    int accM[2][4][4], accC[2][4][4];
#pragma unroll
    for (int i = 0; i < 2; i++)
#pragma unroll
        for (int j = 0; j < 4; j++)
#pragma unroll
            for (int r = 0; r < 4; r++) { accM[i][j][r] = 0; accC[i][j][r] = 0; }

    const int a_row = lane & 15;
    const int a_koffB = ((lane >> 4) << 4);
    const int b_row = (lane & 7) + ((lane & 16) >> 1);
    const int b_koffB = (lane & 8) * 2;

    const int nChunk = K / BK;

    auto issue = [&](int stage, int k0) {
        uint32_t sb = sbase + stage * STAGE;
        {
            int row = tid >> 2;
            int seg = tid & 3;
            uint32_t so = sb + row * PITCH + seg * 16;
            long aoff = (long)(bm + row) * K + k0 + seg * 16;
            cpasync16(so,          g_Aq1 + aoff);
            cpasync16(so + APLANE, g_Aq2 + aoff);
        }
#pragma unroll
        for (int i = 0; i < 2; i++) {
            int idx = tid + i * 256;
            int row = idx >> 2;
            int seg = idx & 3;
            uint32_t so = sb + 2 * APLANE + row * PITCH + seg * 16;
            long boff = (long)(bn + row) * K + k0 + seg * 16;
            cpasync16(so,          Wq1 + boff);
            cpasync16(so + BPLANE, Wq2 + boff);
        }
        asm volatile("cp.async.commit_group;\n" ::: "memory");
    };

    issue(0, 0);
    if (nChunk > 1) issue(1, BK);

    for (int c = 0; c < nChunk; c++) {
        int s = c & 1;
        if (c + 1 < nChunk)
            asm volatile("cp.async.wait_group 1;\n" ::: "memory");
        else
            asm volatile("cp.async.wait_group 0;\n" ::: "memory");
        __syncthreads();

        char* sA1 = smem + s * STAGE;
        char* sA2 = sA1 + APLANE;
        char* sB1 = sA1 + 2 * APLANE;
        char* sB2 = sB1 + BPLANE;

#pragma unroll
        for (int ksB = 0; ksB < 64; ksB += 32) {
            uint32_t aq1[2][4], aq2[2][4];
#pragma unroll
            for (int mt = 0; mt < 2; mt++) {
                int m0 = warp_m * 32 + mt * 16;
                ldsm4(aq1[mt][0], aq1[mt][1], aq1[mt][2], aq1[mt][3],
                      sA1 + (m0 + a_row) * PITCH + ksB + a_koffB);
                ldsm4(aq2[mt][0], aq2[mt][1], aq2[mt][2], aq2[mt][3],
                      sA2 + (m0 + a_row) * PITCH + ksB + a_koffB);
            }
#pragma unroll
            for (int pair = 0; pair < 2; pair++) {
                int n0 = warp_n * 32 + pair * 16;
                uint32_t b1_0, b1_1, b1_2, b1_3, b2_0, b2_1, b2_2, b2_3;
                ldsm4(b1_0, b1_1, b1_2, b1_3, sB1 + (n0 + b_row) * PITCH + ksB + b_koffB);
                ldsm4(b2_0, b2_1, b2_2, b2_3, sB2 + (n0 + b_row) * PITCH + ksB + b_koffB);
#pragma unroll
                for (int mt = 0; mt < 2; mt++) {
                    int* m0p = accM[mt][pair * 2 + 0];
                    int* c0p = accC[mt][pair * 2 + 0];
                    int* m1p = accM[mt][pair * 2 + 1];
                    int* c1p = accC[mt][pair * 2 + 1];
                    imma(m0p, aq1[mt], b1_0, b1_1);
                    imma(c0p, aq1[mt], b2_0, b2_1);
                    imma(c0p, aq2[mt], b1_0, b1_1);
                    imma(m1p, aq1[mt], b1_2, b1_3);
                    imma(c1p, aq1[mt], b2_2, b2_3);
                    imma(c1p, aq2[mt], b1_2, b1_3);
                }
            }
        }
        __syncthreads();

        if (c + 2 < nChunk) issue(s, (c + 2) * BK);
    }

    const int cbase = bn + warp_n * 32 + 2 * (lane & 3);
    constexpr float INV254 = 1.f / 254.f;

    if (OUTX) {
        float* sred = (float*)smem;   // 64 rows x 17 floats, reused pipeline smem
        // pass 1: per-thread local |max| per owned row
        float lm[2][2] = {{0.f, 0.f}, {0.f, 0.f}};
#pragma unroll
        for (int mt = 0; mt < 2; mt++) {
#pragma unroll
            for (int half = 0; half < 2; half++) {
                int r = bm + warp_m * 32 + mt * 16 + half * 8 + (lane >> 2);
                float sa = g_sA[r];
                float bmsk = SCALED ? g_msk[r] : 1.0f;
#pragma unroll
                for (int p = 0; p < 4; p++) {
                    int c = cbase + p * 8;
                    float2 sw = *(const float2*)(g_sW + soff + c);
                    float2 bv = *(const float2*)(bias + c);
                    float v0 = sa * sw.x * ((float)accM[mt][p][half * 2 + 0]
                             + (float)accC[mt][p][half * 2 + 0] * INV254) + bv.x * bmsk;
                    float v1 = sa * sw.y * ((float)accM[mt][p][half * 2 + 1]
                             + (float)accC[mt][p][half * 2 + 1] * INV254) + bv.y * bmsk;
                    if (RELU) { v0 = fmaxf(v0, 0.f); v1 = fmaxf(v1, 0.f); }
                    lm[mt][half] = fmaxf(lm[mt][half], fmaxf(fabsf(v0), fabsf(v1)));
                }
            }
        }
        const int colg = warp_n * 4 + (lane & 3);
#pragma unroll
        for (int mt = 0; mt < 2; mt++)
#pragma unroll
            for (int half = 0; half < 2; half++) {
                int rl = warp_m * 32 + mt * 16 + half * 8 + (lane >> 2);
                sred[rl * 17 + colg] = lm[mt][half];
            }
        __syncthreads();
        if (tid < 64) {
            float m = 0.f;
#pragma unroll
            for (int i = 0; i < 16; i++) m = fmaxf(m, sred[tid * 17 + i]);
            float bs = (m > 0.f) ? m / 127.f : 1.f;
            sred[tid * 17 + 16] = bs;
            g_bs[(long)(bm + tid) * 8 + blockIdx.x] = bs;
        }
        __syncthreads();
        // pass 2: quantize & write int16
#pragma unroll
        for (int mt = 0; mt < 2; mt++) {
#pragma unroll
            for (int half = 0; half < 2; half++) {
                int rl = warp_m * 32 + mt * 16 + half * 8 + (lane >> 2);
                int r = bm + rl;
                float sa = g_sA[r];
                float bmsk = SCALED ? g_msk[r] : 1.0f;
                float f = 254.f / sred[rl * 17 + 16];
#pragma unroll
                for (int p = 0; p < 4; p++) {
                    int c = cbase + p * 8;
                    float2 sw = *(const float2*)(g_sW + soff + c);
                    float2 bv = *(const float2*)(bias + c);
                    float v0 = sa * sw.x * ((float)accM[mt][p][half * 2 + 0]
                             + (float)accC[mt][p][half * 2 + 0] * INV254) + bv.x * bmsk;
                    float v1 = sa * sw.y * ((float)accM[mt][p][half * 2 + 1]
                             + (float)accC[mt][p][half * 2 + 1] * INV254) + bv.y * bmsk;
                    if (RELU) { v0 = fmaxf(v0, 0.f); v1 = fmaxf(v1, 0.f); }
                    short2 o;
                    o.x = (short)(int)rintf(v0 * f);
                    o.y = (short)(int)rintf(v1 * f);
                    *(short2*)(g_Xq + (long)r * N + c) = o;
                }
            }
        }
    } else {
#pragma unroll
        for (int mt = 0; mt < 2; mt++) {
#pragma unroll
            for (int half = 0; half < 2; half++) {
                int r = bm + warp_m * 32 + mt * 16 + half * 8 + (lane >> 2);
                float sa = g_sA[r];
                float bmsk = SCALED ? g_msk[r] : 1.0f;
#pragma unroll
                for (int p = 0; p < 4; p++) {
                    int c = cbase + p * 8;
                    float2 sw = *(const float2*)(g_sW + soff + c);
                    float2 bv = *(const float2*)(bias + c);
                    float v0 = sa * sw.x * ((float)accM[mt][p][half * 2 + 0]
                             + (float)accC[mt][p][half * 2 + 0] * INV254) + bv.x * bmsk;
                    float v1 = sa * sw.y * ((float)accM[mt][p][half * 2 + 1]
                             + (float)accC[mt][p][half * 2 + 1] * INV254) + bv.y * bmsk;
                    if (RELU) { v0 = fmaxf(v0, 0.f); v1 = fmaxf(v1, 0.f); }
                    *(float2*)(g_B + (long)r * N + c) = make_float2(v0, v1);
                }
            }
        }
    }
}

// ---------------- SIMT SGEMM for K=16 first layer (g_H -> g_A) ----------------
__global__ __launch_bounds__(256) void sgemm16_kernel(
    int N, const float* __restrict__ B, const float* __restrict__ bias)
{
    constexpr int BM = 128, BK = 16, TM = 8, TN = 8;
    __shared__ __align__(16) float As[BK][BM];
    __shared__ __align__(16) float Bs[BK][128];
    const int bm = blockIdx.y * BM;
    const int bn = blockIdx.x * 128;
    const int tid = threadIdx.x;
    const int arow = tid >> 2, acol = (tid & 3) << 2;
    const int brow = tid >> 5, bcol = (tid & 31) << 2;
    const int ty = (tid >> 4) * TM, tx = (tid & 15) * TN;
    float acc[TM][TN];
#pragma unroll
    for (int i = 0; i < TM; i++)
#pragma unroll
        for (int j = 0; j < TN; j++) acc[i][j] = 0.f;
    const int K = 16;
#pragma unroll
    for (int i = 0; i < 2; i++) {
        int r = arow + i * 64;
        float4 v = *(const float4*)(g_H + (long)(bm + r) * K + acol);
        As[acol + 0][r] = v.x; As[acol + 1][r] = v.y;
        As[acol + 2][r] = v.z; As[acol + 3][r] = v.w;
    }
#pragma unroll
    for (int i = 0; i < 2; i++) {
        int r = brow + i * 8;
        *(float4*)(&Bs[r][bcol]) = *(const float4*)(B + (long)r * N + bn + bcol);
    }
    __syncthreads();
#pragma unroll
    for (int kk = 0; kk < BK; kk++) {
        float ra[TM], rb[TN];
        *(float4*)(ra)     = *(const float4*)(&As[kk][ty]);
        *(float4*)(ra + 4) = *(const float4*)(&As[kk][ty + 4]);
        *(float4*)(rb)     = *(const float4*)(&Bs[kk][tx]);
        *(float4*)(rb + 4) = *(const float4*)(&Bs[kk][tx + 4]);
#pragma unroll
        for (int i = 0; i < TM; i++)
#pragma unroll
            for (int j = 0; j < TN; j++) acc[i][j] += ra[i] * rb[j];
    }
#pragma unroll
    for (int i = 0; i < TM; i++) {
        long m = bm + ty + i;
        float* crow = g_A + m * N + bn + tx;
#pragma unroll
        for (int j = 0; j < TN; j += 4) {
            float4 bv = *(const float4*)(bias + bn + tx + j);
            float4 o;
            o.x = acc[i][j + 0] + bv.x; o.y = acc[i][j + 1] + bv.y;
            o.z = acc[i][j + 2] + bv.z; o.w = acc[i][j + 3] + bv.w;
            *(float4*)(crow + j) = o;
        }
    }
}

// ---------------- layer-1 only: fp32 g_A rows -> int16 g_Xq + g_bs[row*8] ----------------
__global__ void k_aqX(int N) {
    __shared__ float smax[256];
    int row = blockIdx.x;
    int t = threadIdx.x;
    float4 xv = ((const float4*)(g_A + (long)row * N))[t];
    float m = fmaxf(fmaxf(fabsf(xv.x), fabsf(xv.y)), fmaxf(fabsf(xv.z), fabsf(xv.w)));
    smax[t] = m;
    __syncthreads();
    for (int st = blockDim.x >> 1; st > 0; st >>= 1) {
        if (t < st) smax[t] = fmaxf(smax[t], smax[t + st]);
        __syncthreads();
    }
    float rm = smax[0];
    float sc = (rm > 0.f) ? rm / 127.f : 1.f;
    if (t == 0) g_bs[(long)row * 8] = sc;   // N=128 -> single block
    float f = 254.f / sc;
    short4 q;
    q.x = (short)(int)rintf(xv.x * f);
    q.y = (short)(int)rintf(xv.y * f);
    q.z = (short)(int)rintf(xv.z * f);
    q.w = (short)(int)rintf(xv.w * f);
    ((short4*)(g_Xq + (long)row * N))[t] = q;
}

// ---------------- CSR aggregation, int16 block-scaled gather, fused output double-quant ----------------
template <int H, int RPB>
__global__ __launch_bounds__(256) void k_agg(const float* __restrict__ w1p) {
    constexpr int TPR = H / 4;
    static_assert(TPR * RPB == 256, "block mapping");
    __shared__ __align__(16) float sw0[H];
    __shared__ __align__(16) float sw1[H];
    __shared__ float smax[256];
    for (int i = threadIdx.x; i < H; i += 256) {
        sw0[i] = w1p[i];
        sw1[i] = w1p[H + i];
    }
    __syncthreads();

    const int lr   = threadIdx.x / TPR;
    const int lane = threadIdx.x % TPR;
    const int row  = blockIdx.x * RPB + lr;
    const int v    = lane * 4;
    const int blk  = v >> 7;

    const float4 w0 = *(const float4*)(sw0 + v);
    const float4 w1 = *(const float4*)(sw1 + v);

    const int beg = g_off[row];
    const int end = g_off[row + 1];
    constexpr float INV254 = 1.f / 254.f;

    float4 acc = make_float4(0.f, 0.f, 0.f, 0.f);
    int j = beg;
    for (; j + 2 <= end; j += 2) {
        int s0 = __ldg(g_srcs + j);
        int s1 = __ldg(g_srcs + j + 1);
        float2 r0 = __ldg(g_crel + j);
        float2 r1 = __ldg(g_crel + j + 1);
        float f0 = __ldg(g_bs + (long)s0 * 8 + blk) * INV254;
        float f1 = __ldg(g_bs + (long)s1 * 8 + blk) * INV254;
        int2 q0 = __ldg((const int2*)(g_Xq + (long)s0 * H) + lane);
        int2 q1 = __ldg((const int2*)(g_Xq + (long)s1 * H) + lane);
        float a0x = (float)((short)q0.x) * f0, a0y = (float)(q0.x >> 16) * f0;
        float a0z = (float)((short)q0.y) * f0, a0w = (float)(q0.y >> 16) * f0;
        float a1x = (float)((short)q1.x) * f1, a1y = (float)(q1.x >> 16) * f1;
        float a1z = (float)((short)q1.y) * f1, a1w = (float)(q1.y >> 16) * f1;
        acc.x += fmaxf(fmaf(r0.x, w0.x, fmaf(r0.y, w1.x, a0x)), 0.f);
        acc.y += fmaxf(fmaf(r0.x, w0.y, fmaf(r0.y, w1.y, a0y)), 0.f);
        acc.z += fmaxf(fmaf(r0.x, w0.z, fmaf(r0.y, w1.z, a0z)), 0.f);
        acc.w += fmaxf(fmaf(r0.x, w0.w, fmaf(r0.y, w1.w, a0w)), 0.f);
        acc.x += fmaxf(fmaf(r1.x, w0.x, fmaf(r1.y, w1.x, a1x)), 0.f);
        acc.y += fmaxf(fmaf(r1.x, w0.y, fmaf(r1.y, w1.y, a1y)), 0.f);
        acc.z += fmaxf(fmaf(r1.x, w0.z, fmaf(r1.y, w1.z, a1z)), 0.f);
        acc.w += fmaxf(fmaf(r1.x, w0.w, fmaf(r1.y, w1.w, a1w)), 0.f);
    }
    if (j < end) {
        int s0 = __ldg(g_srcs + j);
        float2 r0 = __ldg(g_crel + j);
        float f0 = __ldg(g_bs + (long)s0 * 8 + blk) * INV254;
        int2 q0 = __ldg((const int2*)(g_Xq + (long)s0 * H) + lane);
        float a0x = (float)((short)q0.x) * f0, a0y = (float)(q0.x >> 16) * f0;
        float a0z = (float)((short)q0.y) * f0, a0w = (float)(q0.y >> 16) * f0;
        acc.x += fmaxf(fmaf(r0.x, w0.x, fmaf(r0.y, w1.x, a0x)), 0.f);
        acc.y += fmaxf(fmaf(r0.x, w0.y, fmaf(r0.y, w1.y, a0y)), 0.f);
        acc.z += fmaxf(fmaf(r0.x, w0.z, fmaf(r0.y, w1.z, a0z)), 0.f);
        acc.w += fmaxf(fmaf(r0.x, w0.w, fmaf(r0.y, w1.w, a0w)), 0.f);
    }
    float s = g_inv[row];
    acc.x *= s; acc.y *= s; acc.z *= s; acc.w *= s;

    smax[threadIdx.x] = fmaxf(fmaxf(acc.x, acc.y), fmaxf(acc.z, acc.w));
    __syncthreads();
    const int gb = lr * TPR;
#pragma unroll
    for (int st = TPR >> 1; st > 0; st >>= 1) {
        if (lane < st) smax[gb + lane] = fmaxf(smax[gb + lane], smax[gb + lane + st]);
        __syncthreads();
    }
    float rm = smax[gb];
    float sc = (rm > 0.f) ? rm / 127.f : 1.f;
    if (lane == 0) g_sA[row] = sc;
    float isc = 1.f / sc;

    int8_t q1[4], q2[4];
    quant2(acc.x * isc, q1[0], q2[0]);
    quant2(acc.y * isc, q1[1], q2[1]);
    quant2(acc.z * isc, q1[2], q2[2]);
    quant2(acc.w * isc, q1[3], q2[3]);
    long o = (long)row * H + v;
    *(char4*)(g_Aq1 + o) = make_char4(q1[0], q1[1], q1[2], q1[3]);
    *(char4*)(g_Aq2 + o) = make_char4(q2[0], q2[1], q2[2], q2[3]);
}

// ---------------- int16 g_Xq rows -> int8 pair g_Aq1/g_Aq2 + row scale g_sA ----------------
__global__ void k_aquant16(int N) {
    __shared__ float smax[256];
    int row = blockIdx.x;
    int t = threadIdx.x;
    constexpr float INV254 = 1.f / 254.f;
    short4 q = ((const short4*)(g_Xq + (long)row * N))[t];
    float f = g_bs[(long)row * 8 + (t >> 5)] * INV254;
    float x0 = (float)q.x * f, x1 = (float)q.y * f;
    float x2 = (float)q.z * f, x3 = (float)q.w * f;
    float m = fmaxf(fmaxf(fabsf(x0), fabsf(x1)), fmaxf(fabsf(x2), fabsf(x3)));
    smax[t] = m;
    __syncthreads();
    for (int st = blockDim.x >> 1; st > 0; st >>= 1) {
        if (t < st) smax[t] = fmaxf(smax[t], smax[t + st]);
        __syncthreads();
    }
    float rm = smax[0];
    float sc = (rm > 0.f) ? rm / 127.f : 1.f;
    if (t == 0) g_sA[row] = sc;
    float isc = 1.f / sc;
    int8_t q1[4], q2[4];
    quant2(x0 * isc, q1[0], q2[0]);
    quant2(x1 * isc, q1[1], q2[1]);
    quant2(x2 * isc, q1[2], q2[2]);
    quant2(x3 * isc, q1[3], q2[3]);
    long o = (long)row * N + t * 4;
    *(char4*)(g_Aq1 + o) = make_char4(q1[0], q1[1], q1[2], q1[3]);
    *(char4*)(g_Aq2 + o) = make_char4(q2[0], q2[1], q2[2], q2[3]);
}

// ---------------- head final: out[M,4] = g_B[M,512] @ W[512,4] + b ----------------
__global__ void k_head_final(const float* __restrict__ W,
                             const float* __restrict__ b, float* __restrict__ out) {
    int warp = (blockIdx.x * blockDim.x + threadIdx.x) >> 5;
    int lane = threadIdx.x & 31;
    if (warp >= NN) return;
    const float* x = g_B + (long)warp * 512;
    float a0 = 0.f, a1 = 0.f, a2 = 0.f, a3 = 0.f;
    for (int k = lane; k < 512; k += 32) {
        float xv = x[k];
        float4 w = *(const float4*)(W + k * 4);
        a0 = fmaf(xv, w.x, a0);
        a1 = fmaf(xv, w.y, a1);
        a2 = fmaf(xv, w.z, a2);
        a3 = fmaf(xv, w.w, a3);
    }
#pragma unroll
    for (int off = 16; off > 0; off >>= 1) {
        a0 += __shfl_down_sync(0xffffffffu, a0, off);
        a1 += __shfl_down_sync(0xffffffffu, a1, off);
        a2 += __shfl_down_sync(0xffffffffu, a2, off);
        a3 += __shfl_down_sync(0xffffffffu, a3, off);
    }
    if (lane == 0) {
        out[warp * 4 + 0] = a0 + b[0];
        out[warp * 4 + 1] = a1 + b[1];
        out[warp * 4 + 2] = a2 + b[2];
        out[warp * 4 + 3] = a3 + b[3];
    }
}

// ---------------- host orchestration ----------------
#define IG_SMEM (2 * 30720)   // 61440

template <bool RELU, bool SCALED, bool OUTX>
static void launch_ig(dim3 grid, int K, int N, long woff, int soff, const float* bias) {
    cudaFuncSetAttribute(igemm_kernel<RELU, SCALED, OUTX>,
                         cudaFuncAttributeMaxDynamicSharedMemorySize, IG_SMEM);
    igemm_kernel<RELU, SCALED, OUTX><<<grid, 256, IG_SMEM>>>(K, N, woff, soff, bias);
}

extern "C" void kernel_launch(void* const* d_in, const int* in_sizes, int n_in,
                              void* d_out, int out_size) {
    const float* h_in = (const float*)d_in[0];
    const float* pos  = (const float*)d_in[1];
    const int*   ei   = (const int*)d_in[2];
    const float* l1_w1 = (const float*)d_in[3];
    const float* l1_b1 = (const float*)d_in[4];
    const float* l1_w2 = (const float*)d_in[5];
    const float* l1_b2 = (const float*)d_in[6];
    const float* l2_w1 = (const float*)d_in[7];
    const float* l2_b1 = (const float*)d_in[8];
    const float* l2_w2 = (const float*)d_in[9];
    const float* l2_b2 = (const float*)d_in[10];
    const float* l3_w1 = (const float*)d_in[11];
    const float* l3_b1 = (const float*)d_in[12];
    const float* l3_w2 = (const float*)d_in[13];
    const float* l3_b2 = (const float*)d_in[14];
    const float* l4_w1 = (const float*)d_in[15];
    const float* l4_b1 = (const float*)d_in[16];
    const float* l4_w2 = (const float*)d_in[17];
    const float* l4_b2 = (const float*)d_in[18];
    const float* hd_w1 = (const float*)d_in[19];
    const float* hd_b1 = (const float*)d_in[20];
    const float* hd_w2 = (const float*)d_in[21];
    const float* hd_b2 = (const float*)d_in[22];
    const float* hd_w3 = (const float*)d_in[23];
    const float* hd_b3 = (const float*)d_in[24];

    // prep: padded copy + CSR build
    k_copy_h<<<(NPAD * 16 / 4 + 255) / 256, 256>>>(h_in);
    k_count<<<(NE + 255) / 256, 256>>>(ei);
    k_scan<<<1, 1024>>>();
    k_scatter<<<(NE + 255) / 256, 256>>>(ei, pos);

    // batched weight quantization
    WTab tab;
    const float* Ws[9] = {l1_w2, l2_w1, l2_w2, l3_w1, l3_w2, l4_w1, l4_w2, hd_w1, hd_w2};
    int Ks[9] = {128, 128, 256, 256, 1024, 1024, 1024, 1024, 1024};
    int Ns[9] = {128, 256, 256, 1024, 1024, 1024, 1024, 1024, 512};
    long wof[9] = {OFF_L1W2, OFF_L2W1, OFF_L2W2, OFF_L3W1, OFF_L3W2,
                   OFF_L4W1, OFF_L4W2, OFF_HDW1, OFF_HDW2};
    int sof[9] = {SOF_L1W2, SOF_L2W1, SOF_L2W2, SOF_L3W1, SOF_L3W2,
                  SOF_L4W1, SOF_L4W2, SOF_HDW1, SOF_HDW2};
    for (int i = 0; i < 9; i++) {
        tab.W[i] = Ws[i]; tab.K[i] = Ks[i]; tab.N[i] = Ns[i];
        tab.woff[i] = wof[i]; tab.soff[i] = sof[i];
    }
    k_wmax_all<<<dim3(4, 8, 9), 256>>>(tab);
    k_wquant_all<<<dim3(32, 32, 9), dim3(32, 8)>>>(tab);

    dim3 g1s(1, NPAD / 128);
    dim3 g128(1, NPAD / 64), g256(2, NPAD / 64), g1024(8, NPAD / 64), g512(4, NPAD / 64);

    // --- layer 1: 16 -> 128 -> 128 ---
    sgemm16_kernel<<<g1s, 256>>>(128, l1_w1, l1_b1);
    k_aqX<<<NPAD, 128 / 4>>>(128);
    k_agg<128, 8><<<NPAD / 8, 256>>>(l1_w1 + 16 * 128);
    launch_ig<true, true, true>(g128, 128, 128, OFF_L1W2, SOF_L1W2, l1_b2);
    k_aquant16<<<NPAD, 128 / 4>>>(128);

    // --- layer 2 ---
    launch_ig<false, false, true>(g256, 128, 256, OFF_L2W1, SOF_L2W1, l2_b1);
    k_agg<256, 4><<<NPAD / 4, 256>>>(l2_w1 + 128 * 256);
    launch_ig<true, true, true>(g256, 256, 256, OFF_L2W2, SOF_L2W2, l2_b2);
    k_aquant16<<<NPAD, 256 / 4>>>(256);

    // --- layer 3 ---
    launch_ig<false, false, true>(g1024, 256, 1024, OFF_L3W1, SOF_L3W1, l3_b1);
    k_agg<1024, 1><<<NPAD, 256>>>(l3_w1 + 256 * 1024);
    launch_ig<true, true, true>(g1024, 1024, 1024, OFF_L3W2, SOF_L3W2, l3_b2);
    k_aquant16<<<NPAD, 1024 / 4>>>(1024);

    // --- layer 4 ---
    launch_ig<false, false, true>(g1024, 1024, 1024, OFF_L4W1, SOF_L4W1, l4_b1);
    k_agg<1024, 1><<<NPAD, 256>>>(l4_w1 + 1024 * 1024);
    launch_ig<true, true, true>(g1024, 1024, 1024, OFF_L4W2, SOF_L4W2, l4_b2);
    k_aquant16<<<NPAD, 1024 / 4>>>(1024);

    // --- head ---
    launch_ig<true, false, true>(g1024, 1024, 1024, OFF_HDW1, SOF_HDW1, hd_b1);
    k_aquant16<<<NPAD, 1024 / 4>>>(1024);
    launch_ig<true, false, false>(g512, 1024, 512, OFF_HDW2, SOF_HDW2, hd_b2);
    k_head_final<<<(NN * 32 + 255) / 256, 256>>>(hd_w3, hd_b3, (float*)d_out);
}